// round 12
// baseline (speedup 1.0000x reference)
#include <cuda_runtime.h>
#include <cuda_fp16.h>
#include <math.h>
#include <stdint.h>

#define BATCH 4
#define SEQ   2048
#define CDIM  384
#define NH    6
#define HD    64
#define NT    (SEQ / 64)          // 32 KV tiles per (b,h)
#define NSPLIT 2
#define NT_HALF (NT / NSPLIT)     // 16 tiles per split
#define NROWS (BATCH * NH * SEQ)  // 49152 q rows total

// Scratch (static __device__ arrays — no runtime allocation allowed).
__device__ float g_q[BATCH*NH*SEQ*HD];
// Pre-swizzled fp16 tile images: [bh][tile][8192 bytes] (ldmatrix-ready).
__device__ uint4 g_kh[BATCH*NH*NT*512];
__device__ uint4 g_vh[BATCH*NH*NT*512];
// Split-KV partials (raw sums; static softmax shift makes them exactly addable).
__device__ float g_po[NSPLIT*NROWS*HD];
__device__ float g_pl[NSPLIT*NROWS];

// ---------------------------------------------------------------------------
// helpers (sm_80-compatible PTX; assembles for sm_100)
// ---------------------------------------------------------------------------
__device__ __forceinline__ uint32_t smem_u32(const void* p) {
    uint32_t a;
    asm("{ .reg .u64 t; cvta.to.shared.u64 t, %1; cvt.u32.u64 %0, t; }"
        : "=r"(a) : "l"(p));
    return a;
}
__device__ __forceinline__ void ldsm_x4(uint32_t& r0, uint32_t& r1,
                                        uint32_t& r2, uint32_t& r3, uint32_t addr) {
    asm volatile("ldmatrix.sync.aligned.m8n8.x4.shared.b16 {%0,%1,%2,%3}, [%4];"
                 : "=r"(r0), "=r"(r1), "=r"(r2), "=r"(r3) : "r"(addr));
}
__device__ __forceinline__ void ldsm_x4_t(uint32_t& r0, uint32_t& r1,
                                          uint32_t& r2, uint32_t& r3, uint32_t addr) {
    asm volatile("ldmatrix.sync.aligned.m8n8.x4.trans.shared.b16 {%0,%1,%2,%3}, [%4];"
                 : "=r"(r0), "=r"(r1), "=r"(r2), "=r"(r3) : "r"(addr));
}
__device__ __forceinline__ void mma16816(float* d,
    uint32_t a0, uint32_t a1, uint32_t a2, uint32_t a3, uint32_t b0, uint32_t b1) {
    asm volatile(
        "mma.sync.aligned.m16n8k16.row.col.f32.f16.f16.f32 "
        "{%0,%1,%2,%3}, {%4,%5,%6,%7}, {%8,%9}, {%0,%1,%2,%3};"
        : "+f"(d[0]), "+f"(d[1]), "+f"(d[2]), "+f"(d[3])
        : "r"(a0), "r"(a1), "r"(a2), "r"(a3), "r"(b0), "r"(b1));
}
__device__ __forceinline__ uint32_t pack_h2(float x, float y) {
    __half2 h = __floats2half2_rn(x, y);
    return *reinterpret_cast<uint32_t*>(&h);
}
__device__ __forceinline__ float lo_res(float x) {
    return x - __half2float(__float2half_rn(x));
}
__device__ __forceinline__ uint32_t sw64(uint32_t off) {
    return off ^ ((off >> 3) & 0x30);
}
__device__ __forceinline__ uint32_t sw128(uint32_t off) {
    return off ^ ((off >> 3) & 0x70);
}
__device__ __forceinline__ void cp_async16(uint32_t dst, const void* src) {
    asm volatile("cp.async.cg.shared.global [%0], [%1], 16;" :: "r"(dst), "l"(src));
}
#define CP_COMMIT() asm volatile("cp.async.commit_group;" ::: "memory")
#define CP_WAIT1()  asm volatile("cp.async.wait_group 1;" ::: "memory")
#define CP_WAIT0()  asm volatile("cp.async.wait_group 0;" ::: "memory")

#define L2E 1.44269504088896f

// ===========================================================================
// Fused QKV GEMM. z derived from blockIdx.x % 3 so the slow 3-split V CTAs
// interleave through every wave (z-major launch order created a slow tail).
//   z=0: g_q fp32 (+ROPE)   z=1: K -> g_kh fp16 pre-swizzled (+ROPE)
//   z=2: V -> g_vh fp16 pre-swizzled, hi/lo 3-split for accuracy
// ===========================================================================
__global__ __launch_bounds__(256, 2)
void gemm_qkv(const float* __restrict__ A,
              const float* __restrict__ Wq,
              const float* __restrict__ Wk,
              const float* __restrict__ Wv,
              const float* __restrict__ cosp,
              const float* __restrict__ sinp)
{
    __shared__ __align__(16) char sAhi[8192];   // [128][32] fp16, 64B rows
    __shared__ __align__(16) char sAlo[8192];
    __shared__ __align__(16) char sWhi[4096];   // [64][32] fp16
    __shared__ __align__(16) char sWlo[4096];

    const int tid  = threadIdx.x;
    const int w    = tid >> 5;
    const int lane = tid & 31;
    const int z     = blockIdx.x % 3;           // interleaved!
    const int rbase = (blockIdx.x / 3) * 128;
    const int jb    = blockIdx.y * 64;
    const bool split3 = (z == 2);
    const float* W = (z == 0) ? Wq : (z == 1) ? Wk : Wv;

    const uint32_t aHi = smem_u32(sAhi);
    const uint32_t aLo = smem_u32(sAlo);
    const uint32_t wHi = smem_u32(sWhi);
    const uint32_t wLo = smem_u32(sWlo);

    float acc[8][4];
    #pragma unroll
    for (int m = 0; m < 8; m++)
        #pragma unroll
        for (int i = 0; i < 4; i++) acc[m][i] = 0.0f;

    const uint32_t aoff = (uint32_t)((w * 16 + (lane & 15)) * 64 + ((lane >> 4) & 1) * 16);
    const int joK = (lane & 7) + ((lane >> 4) & 1) * 8;
    const int doK = ((lane >> 3) & 1) * 8;

    const int rl = tid >> 1;
    const int ko = (tid & 1) * 16;
    const int rw = tid >> 2;
    const int kw = (tid & 3) * 8;

    for (int kb = 0; kb < CDIM; kb += 32) {
        __syncthreads();
        {
            const float* src = A + (size_t)(rbase + rl) * CDIM + kb + ko;
            float4 f0 = *(const float4*)(src + 0);
            float4 f1 = *(const float4*)(src + 4);
            float4 f2 = *(const float4*)(src + 8);
            float4 f3 = *(const float4*)(src + 12);
            uint4 h0, h1;
            h0.x = pack_h2(f0.x, f0.y); h0.y = pack_h2(f0.z, f0.w);
            h0.z = pack_h2(f1.x, f1.y); h0.w = pack_h2(f1.z, f1.w);
            h1.x = pack_h2(f2.x, f2.y); h1.y = pack_h2(f2.z, f2.w);
            h1.z = pack_h2(f3.x, f3.y); h1.w = pack_h2(f3.z, f3.w);
            uint32_t g = (uint32_t)(rl * 64 + ko * 2);
            *(uint4*)(sAhi + sw64(g))      = h0;
            *(uint4*)(sAhi + sw64(g + 16)) = h1;
            if (split3) {
                uint4 l0, l1;
                l0.x = pack_h2(lo_res(f0.x), lo_res(f0.y)); l0.y = pack_h2(lo_res(f0.z), lo_res(f0.w));
                l0.z = pack_h2(lo_res(f1.x), lo_res(f1.y)); l0.w = pack_h2(lo_res(f1.z), lo_res(f1.w));
                l1.x = pack_h2(lo_res(f2.x), lo_res(f2.y)); l1.y = pack_h2(lo_res(f2.z), lo_res(f2.w));
                l1.z = pack_h2(lo_res(f3.x), lo_res(f3.y)); l1.w = pack_h2(lo_res(f3.z), lo_res(f3.w));
                *(uint4*)(sAlo + sw64(g))      = l0;
                *(uint4*)(sAlo + sw64(g + 16)) = l1;
            }
        }
        {
            const float* src = W + (size_t)(jb + rw) * CDIM + kb + kw;
            float4 f0 = *(const float4*)(src + 0);
            float4 f1 = *(const float4*)(src + 4);
            uint4 hh;
            hh.x = pack_h2(f0.x, f0.y); hh.y = pack_h2(f0.z, f0.w);
            hh.z = pack_h2(f1.x, f1.y); hh.w = pack_h2(f1.z, f1.w);
            uint32_t g = (uint32_t)(rw * 64 + kw * 2);
            *(uint4*)(sWhi + sw64(g)) = hh;
            if (split3) {
                uint4 ll;
                ll.x = pack_h2(lo_res(f0.x), lo_res(f0.y)); ll.y = pack_h2(lo_res(f0.z), lo_res(f0.w));
                ll.z = pack_h2(lo_res(f1.x), lo_res(f1.y)); ll.w = pack_h2(lo_res(f1.z), lo_res(f1.w));
                *(uint4*)(sWlo + sw64(g)) = ll;
            }
        }
        __syncthreads();

        #pragma unroll
        for (int kc = 0; kc < 2; kc++) {
            uint32_t ah0, ah1, ah2, ah3;
            ldsm_x4(ah0, ah1, ah2, ah3, aHi + sw64(aoff + kc * 32));
            uint32_t al0, al1, al2, al3;
            if (split3)
                ldsm_x4(al0, al1, al2, al3, aLo + sw64(aoff + kc * 32));
            #pragma unroll
            for (int cg = 0; cg < 4; cg++) {
                uint32_t boff = sw64((uint32_t)((cg * 16 + joK) * 64 + kc * 32 + doK * 2));
                uint32_t bh0, bh1, bh2, bh3;
                ldsm_x4(bh0, bh1, bh2, bh3, wHi + boff);
                mma16816(acc[2*cg],   ah0, ah1, ah2, ah3, bh0, bh1);
                mma16816(acc[2*cg+1], ah0, ah1, ah2, ah3, bh2, bh3);
                if (split3) {
                    mma16816(acc[2*cg],   al0, al1, al2, al3, bh0, bh1);
                    mma16816(acc[2*cg+1], al0, al1, al2, al3, bh2, bh3);
                    uint32_t bl0, bl1, bl2, bl3;
                    ldsm_x4(bl0, bl1, bl2, bl3, wLo + boff);
                    mma16816(acc[2*cg],   ah0, ah1, ah2, ah3, bl0, bl1);
                    mma16816(acc[2*cg+1], ah0, ah1, ah2, ah3, bl2, bl3);
                }
            }
        }
    }

    // ---- epilogue ----
    const int rA = rbase + w * 16 + (lane >> 2);
    const int cb = (lane & 3) * 2;

    #pragma unroll
    for (int rp = 0; rp < 2; rp++) {
        int r = rA + rp * 8;
        int i0 = rp * 2;
        if (z < 2) {   // ROPE + RMSNorm for q/k
            int t = r & (SEQ - 1);
            #pragma unroll
            for (int m = 0; m < 4; m++) {
                int d0 = (m >> 1) * 16 + (m & 1) * 8 + cb;
                float c0 = cosp[t * 32 + d0],     s0 = sinp[t * 32 + d0];
                float c1 = cosp[t * 32 + d0 + 1], s1 = sinp[t * 32 + d0 + 1];
                float x1 = acc[m][i0],     x2 = acc[m+4][i0];
                acc[m][i0]     =  x1 * c0 + x2 * s0;
                acc[m+4][i0]   = -x1 * s0 + x2 * c0;
                float y1 = acc[m][i0+1],   y2 = acc[m+4][i0+1];
                acc[m][i0+1]   =  y1 * c1 + y2 * s1;
                acc[m+4][i0+1] = -y1 * s1 + y2 * c1;
            }
            float ss = 0.0f;
            #pragma unroll
            for (int m = 0; m < 8; m++)
                ss += acc[m][i0]*acc[m][i0] + acc[m][i0+1]*acc[m][i0+1];
            ss += __shfl_xor_sync(0xffffffffu, ss, 1);
            ss += __shfl_xor_sync(0xffffffffu, ss, 2);
            float rn = rsqrtf(ss * (1.0f / HD) + 1.1920929e-07f);
            #pragma unroll
            for (int m = 0; m < 8; m++) { acc[m][i0] *= rn; acc[m][i0+1] *= rn; }
        }
        int bb = r >> 11, t = r & (SEQ - 1);
        int bh = bb * NH + blockIdx.y;
        if (z == 0) {
            float* o = g_q + ((size_t)bh * SEQ + t) * HD;
            #pragma unroll
            for (int m = 0; m < 8; m++) {
                int d0 = (m >> 1) * 16 + (m & 1) * 8 + cb;
                *(float2*)(o + d0) = make_float2(acc[m][i0], acc[m][i0+1]);
            }
        } else {
            int tile = t >> 6, j = t & 63;
            size_t base = ((size_t)(bh * NT + tile)) * 8192;
            char* dh = (char*)(z == 1 ? g_kh : g_vh) + base;
            #pragma unroll
            for (int m = 0; m < 8; m++) {
                int d0 = (m >> 1) * 16 + (m & 1) * 8 + cb;
                uint32_t off = sw128((uint32_t)(j * 128 + d0 * 2));
                *(uint32_t*)(dh + off) = pack_h2(acc[m][i0], acc[m][i0+1]);
            }
        }
    }
}

// ===========================================================================
// Proj GEMM with fused split-KV reduce in the A-loader (no reg pipelining):
//   A[r, c] = (O0 + O1) / (l0 + l1)  read directly from partials.
// ===========================================================================
__global__ __launch_bounds__(256, 2)
void gemm_proj(const float* __restrict__ W, float* __restrict__ outp)
{
    __shared__ __align__(16) char sAhi[8192];
    __shared__ __align__(16) char sAlo[8192];
    __shared__ __align__(16) char sWhi[4096];
    __shared__ __align__(16) char sWlo[4096];

    const int tid  = threadIdx.x;
    const int w    = tid >> 5;
    const int lane = tid & 31;
    const int rbase = blockIdx.x * 128;
    const int jb    = blockIdx.y * 64;

    const uint32_t aHi = smem_u32(sAhi);
    const uint32_t aLo = smem_u32(sAlo);
    const uint32_t wHi = smem_u32(sWhi);
    const uint32_t wLo = smem_u32(sWlo);

    float acc[8][4];
    #pragma unroll
    for (int m = 0; m < 8; m++)
        #pragma unroll
        for (int i = 0; i < 4; i++) acc[m][i] = 0.0f;

    const uint32_t aoff = (uint32_t)((w * 16 + (lane & 15)) * 64 + ((lane >> 4) & 1) * 16);
    const int joK = (lane & 7) + ((lane >> 4) & 1) * 8;
    const int doK = ((lane >> 3) & 1) * 8;

    const int rl = tid >> 1;
    const int ko = (tid & 1) * 16;
    const int rw = tid >> 2;
    const int kw = (tid & 3) * 8;

    const int bb = (rbase + rl) >> 11;
    const int tt = (rbase + rl) & (SEQ - 1);
    const float* srcW = W + (size_t)(jb + rw) * CDIM + kw;

    for (int kb = 0; kb < CDIM; kb += 32) {
        __syncthreads();
        {
            // fused split-KV reduce: A = (O0 + O1) / (l0 + l1)
            int c0 = kb + ko;
            size_t row = ((size_t)(bb * NH + (c0 >> 6))) * SEQ + tt;
            float inv = 1.0f / (g_pl[row] + g_pl[NROWS + row]);
            const float* p0 = g_po + row * HD + (c0 & 63);
            const float* p1 = g_po + (size_t)(NROWS + row) * HD + (c0 & 63);
            float4 a0 = *(const float4*)(p0 + 0),  b0 = *(const float4*)(p1 + 0);
            float4 a1 = *(const float4*)(p0 + 4),  b1 = *(const float4*)(p1 + 4);
            float4 a2 = *(const float4*)(p0 + 8),  b2 = *(const float4*)(p1 + 8);
            float4 a3 = *(const float4*)(p0 + 12), b3 = *(const float4*)(p1 + 12);
            float4 fA0 = make_float4((a0.x+b0.x)*inv, (a0.y+b0.y)*inv, (a0.z+b0.z)*inv, (a0.w+b0.w)*inv);
            float4 fA1 = make_float4((a1.x+b1.x)*inv, (a1.y+b1.y)*inv, (a1.z+b1.z)*inv, (a1.w+b1.w)*inv);
            float4 fA2 = make_float4((a2.x+b2.x)*inv, (a2.y+b2.y)*inv, (a2.z+b2.z)*inv, (a2.w+b2.w)*inv);
            float4 fA3 = make_float4((a3.x+b3.x)*inv, (a3.y+b3.y)*inv, (a3.z+b3.z)*inv, (a3.w+b3.w)*inv);

            uint4 h0, h1, l0, l1;
            h0.x = pack_h2(fA0.x, fA0.y); h0.y = pack_h2(fA0.z, fA0.w);
            h0.z = pack_h2(fA1.x, fA1.y); h0.w = pack_h2(fA1.z, fA1.w);
            h1.x = pack_h2(fA2.x, fA2.y); h1.y = pack_h2(fA2.z, fA2.w);
            h1.z = pack_h2(fA3.x, fA3.y); h1.w = pack_h2(fA3.z, fA3.w);
            l0.x = pack_h2(lo_res(fA0.x), lo_res(fA0.y)); l0.y = pack_h2(lo_res(fA0.z), lo_res(fA0.w));
            l0.z = pack_h2(lo_res(fA1.x), lo_res(fA1.y)); l0.w = pack_h2(lo_res(fA1.z), lo_res(fA1.w));
            l1.x = pack_h2(lo_res(fA2.x), lo_res(fA2.y)); l1.y = pack_h2(lo_res(fA2.z), lo_res(fA2.w));
            l1.z = pack_h2(lo_res(fA3.x), lo_res(fA3.y)); l1.w = pack_h2(lo_res(fA3.z), lo_res(fA3.w));
            uint32_t g = (uint32_t)(rl * 64 + ko * 2);
            *(uint4*)(sAhi + sw64(g))      = h0;
            *(uint4*)(sAhi + sw64(g + 16)) = h1;
            *(uint4*)(sAlo + sw64(g))      = l0;
            *(uint4*)(sAlo + sw64(g + 16)) = l1;
        }
        {
            float4 f0 = *(const float4*)(srcW + kb + 0);
            float4 f1 = *(const float4*)(srcW + kb + 4);
            uint4 hh, ll;
            hh.x = pack_h2(f0.x, f0.y); hh.y = pack_h2(f0.z, f0.w);
            hh.z = pack_h2(f1.x, f1.y); hh.w = pack_h2(f1.z, f1.w);
            ll.x = pack_h2(lo_res(f0.x), lo_res(f0.y)); ll.y = pack_h2(lo_res(f0.z), lo_res(f0.w));
            ll.z = pack_h2(lo_res(f1.x), lo_res(f1.y)); ll.w = pack_h2(lo_res(f1.z), lo_res(f1.w));
            uint32_t g = (uint32_t)(rw * 64 + kw * 2);
            *(uint4*)(sWhi + sw64(g)) = hh;
            *(uint4*)(sWlo + sw64(g)) = ll;
        }
        __syncthreads();

        #pragma unroll
        for (int kc = 0; kc < 2; kc++) {
            uint32_t ah0, ah1, ah2, ah3, al0, al1, al2, al3;
            ldsm_x4(ah0, ah1, ah2, ah3, aHi + sw64(aoff + kc * 32));
            ldsm_x4(al0, al1, al2, al3, aLo + sw64(aoff + kc * 32));
            #pragma unroll
            for (int cg = 0; cg < 4; cg++) {
                uint32_t boff = sw64((uint32_t)((cg * 16 + joK) * 64 + kc * 32 + doK * 2));
                uint32_t bh0, bh1, bh2, bh3;
                ldsm_x4(bh0, bh1, bh2, bh3, wHi + boff);
                mma16816(acc[2*cg],   ah0, ah1, ah2, ah3, bh0, bh1);
                mma16816(acc[2*cg+1], ah0, ah1, ah2, ah3, bh2, bh3);
                mma16816(acc[2*cg],   al0, al1, al2, al3, bh0, bh1);
                mma16816(acc[2*cg+1], al0, al1, al2, al3, bh2, bh3);
                uint32_t bl0, bl1, bl2, bl3;
                ldsm_x4(bl0, bl1, bl2, bl3, wLo + boff);
                mma16816(acc[2*cg],   ah0, ah1, ah2, ah3, bl0, bl1);
                mma16816(acc[2*cg+1], ah0, ah1, ah2, ah3, bl2, bl3);
            }
        }
    }

    const int rA = rbase + w * 16 + (lane >> 2);
    const int cb = (lane & 3) * 2;
    #pragma unroll
    for (int rp = 0; rp < 2; rp++) {
        int r = rA + rp * 8;
        int i0 = rp * 2;
        float* o = outp + (size_t)r * CDIM + jb;
        #pragma unroll
        for (int m = 0; m < 8; m++) {
            int d0 = (m >> 1) * 16 + (m & 1) * 8 + cb;
            *(float2*)(o + d0) = make_float2(acc[m][i0], acc[m][i0+1]);
        }
    }
}

// ===========================================================================
// Flash attention, split-KV x2 (raw-sum partials, exactly addable).
//   Stage (16640 B): Khi[8192] Vhi[8192] mask[256]
// ===========================================================================
#define STAGE_SZ 16640

__global__ __launch_bounds__(256, 2)
void attn_kernel(const int* __restrict__ tmask,
                 const float* __restrict__ mb_raw,
                 const int* __restrict__ bsp)
{
    extern __shared__ __align__(16) char s_dyn[];

    const int tid  = threadIdx.x;
    const int w    = tid >> 5;
    const int lane = tid & 31;
    const int bh   = blockIdx.y;
    const int b    = bh / NH;
    const int h    = bh - b * NH;
    const int qb   = blockIdx.x * 128;
    const int zz   = blockIdx.z;
    const int kt0  = zz * NT_HALF;

    const float* Qg = g_q + (size_t)bh * SEQ * HD;
    const char*  KH = (const char*)g_kh + (size_t)bh * NT * 8192;
    const char*  VH = (const char*)g_vh + (size_t)bh * NT * 8192;
    const int*   MK = tmask + b * SEQ;

    const uint32_t sb0 = smem_u32(s_dyn);

    float bs;
    {
        int iv = bsp[0];
        bs = (iv > -1000000 && iv < 1000000) ? (float)iv : __int_as_float(iv);
    }
    float G1 = 0.5f * tanhf(mb_raw[h * 3 + 0]) * bs;
    float G2 = 0.5f * tanhf(mb_raw[h * 3 + 1]) * bs;
    float G3 = 0.5f * tanhf(mb_raw[h * 3 + 2]) * bs;
    const float b01 = fminf(2.0f, fmaxf(-2.0f, G2));
    const float b10 = fminf(2.0f, fmaxf(-2.0f, G1));
    const float b11 = fminf(2.0f, fmaxf(-2.0f, G1 + G2 + G3));

    const int rA = qb + w * 16 + (lane >> 2);
    const int cb = (lane & 3) * 2;
    const int miA = MK[rA];
    const int miB = MK[rA + 8];
    const float bm0A = ((miA ? b10 : 0.0f) - 4.0f) * L2E;
    const float bm1A = ((miA ? b11 : b01 ) - 4.0f) * L2E;
    const float bm0B = ((miB ? b10 : 0.0f) - 4.0f) * L2E;
    const float bm1B = ((miB ? b11 : b01 ) - 4.0f) * L2E;
    const float SC = 0.125f * L2E;

    uint32_t qhi[16];
    {
        const float* qA = Qg + (size_t)rA * HD + cb;
        const float* qB = qA + 8 * HD;
        #pragma unroll
        for (int kc = 0; kc < 4; kc++) {
            float2 fA0 = *(const float2*)(qA + kc * 16);
            float2 fB0 = *(const float2*)(qB + kc * 16);
            float2 fA1 = *(const float2*)(qA + kc * 16 + 8);
            float2 fB1 = *(const float2*)(qB + kc * 16 + 8);
            qhi[kc*4+0] = pack_h2(fA0.x, fA0.y);
            qhi[kc*4+1] = pack_h2(fB0.x, fB0.y);
            qhi[kc*4+2] = pack_h2(fA1.x, fA1.y);
            qhi[kc*4+3] = pack_h2(fB1.x, fB1.y);
        }
    }

    const int joK = (lane & 7) + ((lane >> 4) & 1) * 8;
    const int doK = ((lane >> 3) & 1) * 8;
    const uint32_t lK = (uint32_t)(joK * 128 + doK * 2);
    const uint32_t xK = (uint32_t)((joK & 7) << 4);
    const int joV = (lane & 7) + ((lane >> 3) & 1) * 8;
    const int doV = ((lane >> 4) & 1) * 8;
    const uint32_t lV = (uint32_t)(joV * 128 + doV * 2);
    const uint32_t xV = (uint32_t)((joV & 7) << 4);

    float o[8][4];
    #pragma unroll
    for (int i = 0; i < 8; i++)
        #pragma unroll
        for (int jx = 0; jx < 4; jx++) o[i][jx] = 0.0f;
    float lA = 0.0f, lB = 0.0f;

    {
        uint32_t sb = sb0;
        size_t toff = (size_t)kt0 * 8192;
        #pragma unroll
        for (int i = 0; i < 2; i++) {
            uint32_t c = (uint32_t)tid * 16 + i * 4096;
            cp_async16(sb + c,        KH + toff + c);
            cp_async16(sb + 8192 + c, VH + toff + c);
        }
        if (tid < 16) cp_async16(sb + 16384 + tid * 16, MK + kt0 * 64 + tid * 4);
        CP_COMMIT();
    }

    for (int ki = 0; ki < NT_HALF; ki++) {
        const int s = ki & 1;
        if (ki + 1 < NT_HALF) {
            uint32_t sb = sb0 + (s ^ 1) * STAGE_SZ;
            size_t toff = (size_t)(kt0 + ki + 1) * 8192;
            #pragma unroll
            for (int i = 0; i < 2; i++) {
                uint32_t c = (uint32_t)tid * 16 + i * 4096;
                cp_async16(sb + c,        KH + toff + c);
                cp_async16(sb + 8192 + c, VH + toff + c);
            }
            if (tid < 16) cp_async16(sb + 16384 + tid * 16, MK + (kt0 + ki + 1) * 64 + tid * 4);
            CP_COMMIT();
            CP_WAIT1();
        } else {
            CP_WAIT0();
        }
        __syncthreads();

        const uint32_t khiA = sb0 + s * STAGE_SZ;
        const uint32_t vhiA = khiA + 8192;
        const int* mjs = (const int*)(s_dyn + s * STAGE_SZ + 16384);

        #pragma unroll
        for (int half = 0; half < 2; half++) {
            float sf[4][4];
            #pragma unroll
            for (int i = 0; i < 4; i++)
                #pragma unroll
                for (int jx = 0; jx < 4; jx++) sf[i][jx] = 0.0f;

            #pragma unroll
            for (int nb2 = 0; nb2 < 2; nb2++) {
                #pragma unroll
                for (int kc = 0; kc < 4; kc++) {
                    uint32_t off = (uint32_t)((half * 2 + nb2) * 2048 + kc * 32) + lK;
                    uint32_t bh0, bh1, bh2, bh3;
                    ldsm_x4(bh0, bh1, bh2, bh3, (khiA + off) ^ xK);
                    mma16816(sf[2*nb2],   qhi[kc*4+0], qhi[kc*4+1], qhi[kc*4+2], qhi[kc*4+3], bh0, bh1);
                    mma16816(sf[2*nb2+1], qhi[kc*4+0], qhi[kc*4+1], qhi[kc*4+2], qhi[kc*4+3], bh2, bh3);
                }
            }

            uint32_t phi[8], plo[8];
            #pragma unroll
            for (int nb = 0; nb < 4; nb++) {
                int j0 = half * 32 + nb * 8 + cb;
                int mj0 = mjs[j0], mj1 = mjs[j0 + 1];
                float bA0 = mj0 ? bm1A : bm0A;
                float bA1 = mj1 ? bm1A : bm0A;
                float bB0 = mj0 ? bm1B : bm0B;
                float bB1 = mj1 ? bm1B : bm0B;
                float pA0 = exp2f(fmaf(sf[nb][0], SC, bA0));
                float pA1 = exp2f(fmaf(sf[nb][1], SC, bA1));
                float pB0 = exp2f(fmaf(sf[nb][2], SC, bB0));
                float pB1 = exp2f(fmaf(sf[nb][3], SC, bB1));
                lA += pA0 + pA1;
                lB += pB0 + pB1;
                phi[nb*2+0] = pack_h2(pA0, pA1);
                phi[nb*2+1] = pack_h2(pB0, pB1);
                plo[nb*2+0] = pack_h2(lo_res(pA0), lo_res(pA1));
                plo[nb*2+1] = pack_h2(lo_res(pB0), lo_res(pB1));
            }

            #pragma unroll
            for (int db2 = 0; db2 < 4; db2++) {
                #pragma unroll
                for (int kc = 0; kc < 2; kc++) {
                    uint32_t off = (uint32_t)((half * 2 + kc) * 2048 + db2 * 32) + lV;
                    uint32_t v0, v1, v2, v3;
                    ldsm_x4_t(v0, v1, v2, v3, (vhiA + off) ^ xV);
                    mma16816(o[2*db2],   phi[4*kc+0], phi[4*kc+1], phi[4*kc+2], phi[4*kc+3], v0, v1);
                    mma16816(o[2*db2+1], phi[4*kc+0], phi[4*kc+1], phi[4*kc+2], phi[4*kc+3], v2, v3);
                    mma16816(o[2*db2],   plo[4*kc+0], plo[4*kc+1], plo[4*kc+2], plo[4*kc+3], v0, v1);
                    mma16816(o[2*db2+1], plo[4*kc+0], plo[4*kc+1], plo[4*kc+2], plo[4*kc+3], v2, v3);
                }
            }
        }
        __syncthreads();
    }

    // ---- write raw partials (no divide) ----
    lA += __shfl_xor_sync(0xffffffffu, lA, 1);
    lA += __shfl_xor_sync(0xffffffffu, lA, 2);
    lB += __shfl_xor_sync(0xffffffffu, lB, 1);
    lB += __shfl_xor_sync(0xffffffffu, lB, 2);

    size_t rowA = (size_t)bh * SEQ + rA;
    float* pA = g_po + ((size_t)zz * NROWS + rowA) * HD + cb;
    float* pB = pA + 8 * HD;
    #pragma unroll
    for (int db = 0; db < 8; db++) {
        *(float2*)(pA + db * 8) = make_float2(o[db][0], o[db][1]);
        *(float2*)(pB + db * 8) = make_float2(o[db][2], o[db][3]);
    }
    if ((lane & 3) == 0) {
        g_pl[(size_t)zz * NROWS + rowA]     = lA;
        g_pl[(size_t)zz * NROWS + rowA + 8] = lB;
    }
}

// ---------------------------------------------------------------------------
extern "C" void kernel_launch(void* const* d_in, const int* in_sizes, int n_in,
                              void* d_out, int out_size)
{
    const float* x    = (const float*)d_in[0];
    const float* cosp = (const float*)d_in[1];
    const float* sinp = (const float*)d_in[2];
    const int*   tmsk = (const int*)  d_in[3];
    const float* Wq   = (const float*)d_in[4];
    const float* Wk   = (const float*)d_in[5];
    const float* Wv   = (const float*)d_in[6];
    const float* Wpr  = (const float*)d_in[7];
    const float* mbr  = (const float*)d_in[8];
    const int*   bsp  = (const int*)  d_in[9];
    float* out = (float*)d_out;

    cudaFuncSetAttribute(attn_kernel,
                         cudaFuncAttributeMaxDynamicSharedMemorySize, 2 * STAGE_SZ);

    gemm_qkv<<<dim3(BATCH * SEQ / 128 * 3, NH), 256>>>(x, Wq, Wk, Wv, cosp, sinp);

    attn_kernel<<<dim3(SEQ / 128, BATCH * NH, NSPLIT), 256, 2 * STAGE_SZ>>>(tmsk, mbr, bsp);

    gemm_proj<<<dim3(BATCH * SEQ / 128, NH), 256>>>(Wpr, out);
}

// round 14
// speedup vs baseline: 1.2611x; 1.2611x over previous
#include <cuda_runtime.h>
#include <cuda_fp16.h>
#include <math.h>
#include <stdint.h>

#define BATCH 4
#define SEQ   2048
#define CDIM  384
#define NH    6
#define HD    64
#define NT    (SEQ / 64)            // 32 KV tiles per (b,h)
#define NRX   (BATCH * SEQ)         // 8192 rows of x / y
#define NRT   (NRX / 128)           // 64 row-tiles
#define NKB   (CDIM / 32)           // 12 k-blocks
#define NJT   (CDIM / 64)           // 6 j-tiles per weight matrix

// Scratch (static __device__ arrays; referenced ONLY from device code).
__device__ float g_q[BATCH*NH*SEQ*HD];
// K/V fp16 tile images for attention (sw128, ldmatrix-ready).
__device__ uint4 g_kh[BATCH*NH*NT*512];
__device__ uint4 g_vh[BATCH*NH*NT*512];
// Pre-converted GEMM operand images (sw64, ldsm-ready).
__device__ char g_xh[NRT*NKB*8192];
__device__ char g_xl[NRT*NKB*8192];
__device__ char g_yh[NRT*NKB*8192];
__device__ char g_yl[NRT*NKB*8192];
__device__ char g_wh[4*NJT*NKB*4096];
__device__ char g_wl[4*NJT*NKB*4096];

// ---------------------------------------------------------------------------
// helpers (sm_80-compatible PTX; assembles for sm_100)
// ---------------------------------------------------------------------------
__device__ __forceinline__ uint32_t smem_u32(const void* p) {
    uint32_t a;
    asm("{ .reg .u64 t; cvta.to.shared.u64 t, %1; cvt.u32.u64 %0, t; }"
        : "=r"(a) : "l"(p));
    return a;
}
__device__ __forceinline__ void ldsm_x4(uint32_t& r0, uint32_t& r1,
                                        uint32_t& r2, uint32_t& r3, uint32_t addr) {
    asm volatile("ldmatrix.sync.aligned.m8n8.x4.shared.b16 {%0,%1,%2,%3}, [%4];"
                 : "=r"(r0), "=r"(r1), "=r"(r2), "=r"(r3) : "r"(addr));
}
__device__ __forceinline__ void ldsm_x4_t(uint32_t& r0, uint32_t& r1,
                                          uint32_t& r2, uint32_t& r3, uint32_t addr) {
    asm volatile("ldmatrix.sync.aligned.m8n8.x4.trans.shared.b16 {%0,%1,%2,%3}, [%4];"
                 : "=r"(r0), "=r"(r1), "=r"(r2), "=r"(r3) : "r"(addr));
}
__device__ __forceinline__ void mma16816(float* d,
    uint32_t a0, uint32_t a1, uint32_t a2, uint32_t a3, uint32_t b0, uint32_t b1) {
    asm volatile(
        "mma.sync.aligned.m16n8k16.row.col.f32.f16.f16.f32 "
        "{%0,%1,%2,%3}, {%4,%5,%6,%7}, {%8,%9}, {%0,%1,%2,%3};"
        : "+f"(d[0]), "+f"(d[1]), "+f"(d[2]), "+f"(d[3])
        : "r"(a0), "r"(a1), "r"(a2), "r"(a3), "r"(b0), "r"(b1));
}
__device__ __forceinline__ uint32_t pack_h2(float x, float y) {
    __half2 h = __floats2half2_rn(x, y);
    return *reinterpret_cast<uint32_t*>(&h);
}
__device__ __forceinline__ float lo_res(float x) {
    return x - __half2float(__float2half_rn(x));
}
__device__ __forceinline__ uint32_t sw64(uint32_t off) {
    return off ^ ((off >> 3) & 0x30);
}
__device__ __forceinline__ uint32_t sw128(uint32_t off) {
    return off ^ ((off >> 3) & 0x70);
}
__device__ __forceinline__ void cp_async16(uint32_t dst, const void* src) {
    asm volatile("cp.async.cg.shared.global [%0], [%1], 16;" :: "r"(dst), "l"(src));
}
#define CP_COMMIT() asm volatile("cp.async.commit_group;" ::: "memory")
#define CP_WAIT1()  asm volatile("cp.async.wait_group 1;" ::: "memory")
#define CP_WAIT0()  asm volatile("cp.async.wait_group 0;" ::: "memory")

// ===========================================================================
// Conversion kernel: fp32 -> pre-swizzled fp16 hi/lo tile images.
//   blocks [0, 768):    x  (rt = b/12, kb = b%12), 128x32 tile -> 8KB block
//   blocks [768, 1056): W  (mat 0..3, jt, kb),      64x32 tile -> 4KB block
// ===========================================================================
__global__ __launch_bounds__(256)
void conv_kernel(const float* __restrict__ x,
                 const float* __restrict__ Wq,
                 const float* __restrict__ Wk,
                 const float* __restrict__ Wv,
                 const float* __restrict__ Wp)
{
    const int bid = blockIdx.x;
    const int tid = threadIdx.x;
    if (bid < NRT * NKB) {
        int rt = bid / NKB, kb = bid - rt * NKB;
        int rl = tid >> 1, ko = (tid & 1) * 16;
        const float* src = x + (size_t)(rt * 128 + rl) * CDIM + kb * 32 + ko;
        float4 f0 = *(const float4*)(src + 0);
        float4 f1 = *(const float4*)(src + 4);
        float4 f2 = *(const float4*)(src + 8);
        float4 f3 = *(const float4*)(src + 12);
        uint4 h0, h1, l0, l1;
        h0.x = pack_h2(f0.x, f0.y); h0.y = pack_h2(f0.z, f0.w);
        h0.z = pack_h2(f1.x, f1.y); h0.w = pack_h2(f1.z, f1.w);
        h1.x = pack_h2(f2.x, f2.y); h1.y = pack_h2(f2.z, f2.w);
        h1.z = pack_h2(f3.x, f3.y); h1.w = pack_h2(f3.z, f3.w);
        l0.x = pack_h2(lo_res(f0.x), lo_res(f0.y)); l0.y = pack_h2(lo_res(f0.z), lo_res(f0.w));
        l0.z = pack_h2(lo_res(f1.x), lo_res(f1.y)); l0.w = pack_h2(lo_res(f1.z), lo_res(f1.w));
        l1.x = pack_h2(lo_res(f2.x), lo_res(f2.y)); l1.y = pack_h2(lo_res(f2.z), lo_res(f2.w));
        l1.z = pack_h2(lo_res(f3.x), lo_res(f3.y)); l1.w = pack_h2(lo_res(f3.z), lo_res(f3.w));
        char* dh = g_xh + (size_t)bid * 8192;
        char* dl = g_xl + (size_t)bid * 8192;
        uint32_t g = (uint32_t)(rl * 64 + ko * 2);
        *(uint4*)(dh + sw64(g))      = h0;
        *(uint4*)(dh + sw64(g + 16)) = h1;
        *(uint4*)(dl + sw64(g))      = l0;
        *(uint4*)(dl + sw64(g + 16)) = l1;
    } else {
        int idx = bid - NRT * NKB;
        int mat = idx / (NJT * NKB);
        int r   = idx - mat * (NJT * NKB);
        int jt = r / NKB, kb = r - jt * NKB;
        int rw = tid >> 2, kw = (tid & 3) * 8;
        const float* Wm = (mat == 0) ? Wq : (mat == 1) ? Wk : (mat == 2) ? Wv : Wp;
        const float* src = Wm + (size_t)(jt * 64 + rw) * CDIM + kb * 32 + kw;
        float4 f0 = *(const float4*)(src + 0);
        float4 f1 = *(const float4*)(src + 4);
        uint4 hh, ll;
        hh.x = pack_h2(f0.x, f0.y); hh.y = pack_h2(f0.z, f0.w);
        hh.z = pack_h2(f1.x, f1.y); hh.w = pack_h2(f1.z, f1.w);
        ll.x = pack_h2(lo_res(f0.x), lo_res(f0.y)); ll.y = pack_h2(lo_res(f0.z), lo_res(f0.w));
        ll.z = pack_h2(lo_res(f1.x), lo_res(f1.y)); ll.w = pack_h2(lo_res(f1.z), lo_res(f1.w));
        char* dh = g_wh + (size_t)idx * 4096;
        char* dl = g_wl + (size_t)idx * 4096;
        uint32_t g = (uint32_t)(rw * 64 + kw * 2);
        *(uint4*)(dh + sw64(g)) = hh;
        *(uint4*)(dl + sw64(g)) = ll;
    }
}

// ===========================================================================
// Image-fed GEMM: pure cp.async (double-buffered) + ldsm + mma.
//   All global pointers resolved IN DEVICE CODE from selector args.
//   ASRC 0: A = x-images.  ASRC 1: A = y-images.
//   SPLIT 1: A-hi * W-hi only.  SPLIT 3: hh + lh + hl (~fp32).
//   DST 0: g_q (+ROPE)  1: g_kh (+ROPE)  2: g_vh  3: outp fp32 [B,T,C]
// ===========================================================================
template<int SPLIT, int ASRC, int DST, bool ROPE>
__global__ __launch_bounds__(256)
void gemm_img(int mat,
              const float* __restrict__ cosp, const float* __restrict__ sinp,
              float* __restrict__ outp)
{
    constexpr int OFF_ALO = 8192;
    constexpr int OFF_WHI = (SPLIT == 3) ? 16384 : 8192;
    constexpr int OFF_WLO = 20480;
    constexpr int STG     = (SPLIT == 3) ? 24576 : 12288;
    __shared__ __align__(16) char sbuf[2 * STG];

    const int tid  = threadIdx.x;
    const int w    = tid >> 5;
    const int lane = tid & 31;
    const int rt   = blockIdx.x;
    const int jt   = blockIdx.y;

    const char* Ahi = (ASRC ? g_yh : g_xh) + (size_t)(rt * NKB) * 8192;
    const char* Alo = (ASRC ? g_yl : g_xl) + (size_t)(rt * NKB) * 8192;
    const char* Whi = g_wh + (size_t)((mat * NJT + jt) * NKB) * 4096;
    const char* Wlo = g_wl + (size_t)((mat * NJT + jt) * NKB) * 4096;

    const uint32_t sbA = smem_u32(sbuf);

    float acc[8][4];
    #pragma unroll
    for (int m = 0; m < 8; m++)
        #pragma unroll
        for (int i = 0; i < 4; i++) acc[m][i] = 0.0f;

    const uint32_t aoff = (uint32_t)((w * 16 + (lane & 15)) * 64 + ((lane >> 4) & 1) * 16);
    const int joK = (lane & 7) + ((lane >> 4) & 1) * 8;
    const int doK = ((lane >> 3) & 1) * 8;

    // ---- prefetch kb = 0 ----
    {
        uint32_t sb = sbA;
        cp_async16(sb + tid * 16,           Ahi + tid * 16);
        cp_async16(sb + 4096 + tid * 16,    Ahi + 4096 + tid * 16);
        cp_async16(sb + OFF_WHI + tid * 16, Whi + tid * 16);
        if (SPLIT == 3) {
            cp_async16(sb + OFF_ALO + tid * 16,        Alo + tid * 16);
            cp_async16(sb + OFF_ALO + 4096 + tid * 16, Alo + 4096 + tid * 16);
            cp_async16(sb + OFF_WLO + tid * 16,        Wlo + tid * 16);
        }
        CP_COMMIT();
    }

    for (int kb = 0; kb < NKB; kb++) {
        const int s = kb & 1;
        if (kb + 1 < NKB) {
            uint32_t sb = sbA + (s ^ 1) * STG;
            size_t ao = (size_t)(kb + 1) * 8192;
            size_t wo = (size_t)(kb + 1) * 4096;
            cp_async16(sb + tid * 16,           Ahi + ao + tid * 16);
            cp_async16(sb + 4096 + tid * 16,    Ahi + ao + 4096 + tid * 16);
            cp_async16(sb + OFF_WHI + tid * 16, Whi + wo + tid * 16);
            if (SPLIT == 3) {
                cp_async16(sb + OFF_ALO + tid * 16,        Alo + ao + tid * 16);
                cp_async16(sb + OFF_ALO + 4096 + tid * 16, Alo + ao + 4096 + tid * 16);
                cp_async16(sb + OFF_WLO + tid * 16,        Wlo + wo + tid * 16);
            }
            CP_COMMIT();
            CP_WAIT1();
        } else {
            CP_WAIT0();
        }
        __syncthreads();

        const uint32_t aHi = sbA + s * STG;
        const uint32_t aLo = aHi + OFF_ALO;
        const uint32_t wHi = aHi + OFF_WHI;
        const uint32_t wLo = aHi + OFF_WLO;

        #pragma unroll
        for (int kc = 0; kc < 2; kc++) {
            uint32_t ah0, ah1, ah2, ah3;
            ldsm_x4(ah0, ah1, ah2, ah3, aHi + sw64(aoff + kc * 32));
            uint32_t al0, al1, al2, al3;
            if (SPLIT == 3)
                ldsm_x4(al0, al1, al2, al3, aLo + sw64(aoff + kc * 32));
            #pragma unroll
            for (int cg = 0; cg < 4; cg++) {
                uint32_t boff = sw64((uint32_t)((cg * 16 + joK) * 64 + kc * 32 + doK * 2));
                uint32_t bh0, bh1, bh2, bh3;
                ldsm_x4(bh0, bh1, bh2, bh3, wHi + boff);
                mma16816(acc[2*cg],   ah0, ah1, ah2, ah3, bh0, bh1);
                mma16816(acc[2*cg+1], ah0, ah1, ah2, ah3, bh2, bh3);
                if (SPLIT == 3) {
                    mma16816(acc[2*cg],   al0, al1, al2, al3, bh0, bh1);
                    mma16816(acc[2*cg+1], al0, al1, al2, al3, bh2, bh3);
                    uint32_t bl0, bl1, bl2, bl3;
                    ldsm_x4(bl0, bl1, bl2, bl3, wLo + boff);
                    mma16816(acc[2*cg],   ah0, ah1, ah2, ah3, bl0, bl1);
                    mma16816(acc[2*cg+1], ah0, ah1, ah2, ah3, bl2, bl3);
                }
            }
        }
        __syncthreads();
    }

    // ---- epilogue ----
    const int rbase = rt * 128;
    const int jb    = jt * 64;
    const int rA = rbase + w * 16 + (lane >> 2);
    const int cb = (lane & 3) * 2;

    #pragma unroll
    for (int rp = 0; rp < 2; rp++) {
        int r = rA + rp * 8;
        int i0 = rp * 2;
        if (ROPE) {
            int t = r & (SEQ - 1);
            #pragma unroll
            for (int m = 0; m < 4; m++) {
                int d0 = (m >> 1) * 16 + (m & 1) * 8 + cb;
                float c0 = cosp[t * 32 + d0],     s0 = sinp[t * 32 + d0];
                float c1 = cosp[t * 32 + d0 + 1], s1 = sinp[t * 32 + d0 + 1];
                float x1 = acc[m][i0],     x2 = acc[m+4][i0];
                acc[m][i0]     =  x1 * c0 + x2 * s0;
                acc[m+4][i0]   = -x1 * s0 + x2 * c0;
                float y1 = acc[m][i0+1],   y2 = acc[m+4][i0+1];
                acc[m][i0+1]   =  y1 * c1 + y2 * s1;
                acc[m+4][i0+1] = -y1 * s1 + y2 * c1;
            }
            float ss = 0.0f;
            #pragma unroll
            for (int m = 0; m < 8; m++)
                ss += acc[m][i0]*acc[m][i0] + acc[m][i0+1]*acc[m][i0+1];
            ss += __shfl_xor_sync(0xffffffffu, ss, 1);
            ss += __shfl_xor_sync(0xffffffffu, ss, 2);
            float rn = rsqrtf(ss * (1.0f / HD) + 1.1920929e-07f);
            #pragma unroll
            for (int m = 0; m < 8; m++) { acc[m][i0] *= rn; acc[m][i0+1] *= rn; }
        }
        if (DST == 3) {
            float* o = outp + (size_t)r * CDIM + jb;
            #pragma unroll
            for (int m = 0; m < 8; m++) {
                int d0 = (m >> 1) * 16 + (m & 1) * 8 + cb;
                *(float2*)(o + d0) = make_float2(acc[m][i0], acc[m][i0+1]);
            }
        } else if (DST == 0) {
            int bb = r >> 11, t = r & (SEQ - 1);
            float* o = g_q + ((size_t)(bb * NH + jt) * SEQ + t) * HD;
            #pragma unroll
            for (int m = 0; m < 8; m++) {
                int d0 = (m >> 1) * 16 + (m & 1) * 8 + cb;
                *(float2*)(o + d0) = make_float2(acc[m][i0], acc[m][i0+1]);
            }
        } else {
            int bb = r >> 11, t = r & (SEQ - 1);
            int bh = bb * NH + jt;
            int tile = t >> 6, j = t & 63;
            size_t base = ((size_t)(bh * NT + tile)) * 8192;
            char* dh = (char*)(DST == 1 ? g_kh : g_vh) + base;
            #pragma unroll
            for (int m = 0; m < 8; m++) {
                int d0 = (m >> 1) * 16 + (m & 1) * 8 + cb;
                uint32_t off = sw128((uint32_t)(j * 128 + d0 * 2));
                *(uint32_t*)(dh + off) = pack_h2(acc[m][i0], acc[m][i0+1]);
            }
        }
    }
}

// ===========================================================================
// Flash attention (R8 structure, proven): full KV loop, __expf, -4 shift.
// Epilogue writes y as fp16 hi/lo sw64 images (same values R8's proj computed).
//   Stage (16640 B): Khi[8192] Vhi[8192] mask[256]
// ===========================================================================
#define STAGE_SZ 16640

__global__ __launch_bounds__(256, 2)
void attn_kernel(const int* __restrict__ tmask,
                 const float* __restrict__ mb_raw,
                 const int* __restrict__ bsp)
{
    extern __shared__ __align__(16) char s_dyn[];

    const int tid  = threadIdx.x;
    const int w    = tid >> 5;
    const int lane = tid & 31;
    const int bh   = blockIdx.y;
    const int b    = bh / NH;
    const int h    = bh - b * NH;
    const int qb   = blockIdx.x * 128;

    const float* Qg = g_q + (size_t)bh * SEQ * HD;
    const char*  KH = (const char*)g_kh + (size_t)bh * NT * 8192;
    const char*  VH = (const char*)g_vh + (size_t)bh * NT * 8192;
    const int*   MK = tmask + b * SEQ;

    const uint32_t sb0 = smem_u32(s_dyn);

    float bs;
    {
        int iv = bsp[0];
        bs = (iv > -1000000 && iv < 1000000) ? (float)iv : __int_as_float(iv);
    }
    float G1 = 0.5f * tanhf(mb_raw[h * 3 + 0]) * bs;
    float G2 = 0.5f * tanhf(mb_raw[h * 3 + 1]) * bs;
    float G3 = 0.5f * tanhf(mb_raw[h * 3 + 2]) * bs;
    const float b01 = fminf(2.0f, fmaxf(-2.0f, G2));
    const float b10 = fminf(2.0f, fmaxf(-2.0f, G1));
    const float b11 = fminf(2.0f, fmaxf(-2.0f, G1 + G2 + G3));

    const int rA = qb + w * 16 + (lane >> 2);
    const int cb = (lane & 3) * 2;
    const int miA = MK[rA];
    const int miB = MK[rA + 8];
    const float bm0A = (miA ? b10 : 0.0f) - 4.0f;
    const float bm1A = (miA ? b11 : b01 ) - 4.0f;
    const float bm0B = (miB ? b10 : 0.0f) - 4.0f;
    const float bm1B = (miB ? b11 : b01 ) - 4.0f;

    uint32_t qhi[16];
    {
        const float* qA = Qg + (size_t)rA * HD + cb;
        const float* qB = qA + 8 * HD;
        #pragma unroll
        for (int kc = 0; kc < 4; kc++) {
            float2 fA0 = *(const float2*)(qA + kc * 16);
            float2 fB0 = *(const float2*)(qB + kc * 16);
            float2 fA1 = *(const float2*)(qA + kc * 16 + 8);
            float2 fB1 = *(const float2*)(qB + kc * 16 + 8);
            qhi[kc*4+0] = pack_h2(fA0.x, fA0.y);
            qhi[kc*4+1] = pack_h2(fB0.x, fB0.y);
            qhi[kc*4+2] = pack_h2(fA1.x, fA1.y);
            qhi[kc*4+3] = pack_h2(fB1.x, fB1.y);
        }
    }

    const int joK = (lane & 7) + ((lane >> 4) & 1) * 8;
    const int doK = ((lane >> 3) & 1) * 8;
    const uint32_t lK = (uint32_t)(joK * 128 + doK * 2);
    const uint32_t xK = (uint32_t)((joK & 7) << 4);
    const int joV = (lane & 7) + ((lane >> 3) & 1) * 8;
    const int doV = ((lane >> 4) & 1) * 8;
    const uint32_t lV = (uint32_t)(joV * 128 + doV * 2);
    const uint32_t xV = (uint32_t)((joV & 7) << 4);

    float o[8][4];
    #pragma unroll
    for (int i = 0; i < 8; i++)
        #pragma unroll
        for (int jx = 0; jx < 4; jx++) o[i][jx] = 0.0f;
    float lA = 0.0f, lB = 0.0f;

    {
        uint32_t sb = sb0;
        #pragma unroll
        for (int i = 0; i < 2; i++) {
            uint32_t c = (uint32_t)tid * 16 + i * 4096;
            cp_async16(sb + c,        KH + c);
            cp_async16(sb + 8192 + c, VH + c);
        }
        if (tid < 16) cp_async16(sb + 16384 + tid * 16, MK + tid * 4);
        CP_COMMIT();
    }

    for (int kt = 0; kt < NT; kt++) {
        const int s = kt & 1;
        if (kt + 1 < NT) {
            uint32_t sb = sb0 + (s ^ 1) * STAGE_SZ;
            size_t toff = (size_t)(kt + 1) * 8192;
            #pragma unroll
            for (int i = 0; i < 2; i++) {
                uint32_t c = (uint32_t)tid * 16 + i * 4096;
                cp_async16(sb + c,        KH + toff + c);
                cp_async16(sb + 8192 + c, VH + toff + c);
            }
            if (tid < 16) cp_async16(sb + 16384 + tid * 16, MK + (kt + 1) * 64 + tid * 4);
            CP_COMMIT();
            CP_WAIT1();
        } else {
            CP_WAIT0();
        }
        __syncthreads();

        const uint32_t khiA = sb0 + s * STAGE_SZ;
        const uint32_t vhiA = khiA + 8192;
        const int* mjs = (const int*)(s_dyn + s * STAGE_SZ + 16384);

        #pragma unroll
        for (int half = 0; half < 2; half++) {
            float sf[4][4];
            #pragma unroll
            for (int i = 0; i < 4; i++)
                #pragma unroll
                for (int jx = 0; jx < 4; jx++) sf[i][jx] = 0.0f;

            #pragma unroll
            for (int nb2 = 0; nb2 < 2; nb2++) {
                #pragma unroll
                for (int kc = 0; kc < 4; kc++) {
                    uint32_t off = (uint32_t)((half * 2 + nb2) * 2048 + kc * 32) + lK;
                    uint32_t bh0, bh1, bh2, bh3;
                    ldsm_x4(bh0, bh1, bh2, bh3, (khiA + off) ^ xK);
                    mma16816(sf[2*nb2],   qhi[kc*4+0], qhi[kc*4+1], qhi[kc*4+2], qhi[kc*4+3], bh0, bh1);
                    mma16816(sf[2*nb2+1], qhi[kc*4+0], qhi[kc*4+1], qhi[kc*4+2], qhi[kc*4+3], bh2, bh3);
                }
            }

            uint32_t phi[8], plo[8];
            #pragma unroll
            for (int nb = 0; nb < 4; nb++) {
                int j0 = half * 32 + nb * 8 + cb;
                int mj0 = mjs[j0], mj1 = mjs[j0 + 1];
                float bA0 = mj0 ? bm1A : bm0A;
                float bA1 = mj1 ? bm1A : bm0A;
                float bB0 = mj0 ? bm1B : bm0B;
                float bB1 = mj1 ? bm1B : bm0B;
                float pA0 = __expf(fmaf(sf[nb][0], 0.125f, bA0));
                float pA1 = __expf(fmaf(sf[nb][1], 0.125f, bA1));
                float pB0 = __expf(fmaf(sf[nb][2], 0.125f, bB0));
                float pB1 = __expf(fmaf(sf[nb][3], 0.125f, bB1));
                lA += pA0 + pA1;
                lB += pB0 + pB1;
                phi[nb*2+0] = pack_h2(pA0, pA1);
                phi[nb*2+1] = pack_h2(pB0, pB1);
                plo[nb*2+0] = pack_h2(lo_res(pA0), lo_res(pA1));
                plo[nb*2+1] = pack_h2(lo_res(pB0), lo_res(pB1));
            }

            #pragma unroll
            for (int db2 = 0; db2 < 4; db2++) {
                #pragma unroll
                for (int kc = 0; kc < 2; kc++) {
                    uint32_t off = (uint32_t)((half * 2 + kc) * 2048 + db2 * 32) + lV;
                    uint32_t v0, v1, v2, v3;
                    ldsm_x4_t(v0, v1, v2, v3, (vhiA + off) ^ xV);
                    mma16816(o[2*db2],   phi[4*kc+0], phi[4*kc+1], phi[4*kc+2], phi[4*kc+3], v0, v1);
                    mma16816(o[2*db2+1], phi[4*kc+0], phi[4*kc+1], phi[4*kc+2], phi[4*kc+3], v2, v3);
                    mma16816(o[2*db2],   plo[4*kc+0], plo[4*kc+1], plo[4*kc+2], plo[4*kc+3], v0, v1);
                    mma16816(o[2*db2+1], plo[4*kc+0], plo[4*kc+1], plo[4*kc+2], plo[4*kc+3], v2, v3);
                }
            }
        }
        __syncthreads();
    }

    // ---- epilogue: normalize and write fp16 hi/lo y-images ----
    lA += __shfl_xor_sync(0xffffffffu, lA, 1);
    lA += __shfl_xor_sync(0xffffffffu, lA, 2);
    lB += __shfl_xor_sync(0xffffffffu, lB, 1);
    lB += __shfl_xor_sync(0xffffffffu, lB, 2);
    float iA = 1.0f / lA, iB = 1.0f / lB;

    #pragma unroll
    for (int rp = 0; rp < 2; rp++) {
        int t = rA + rp * 8;
        float inv = rp ? iB : iA;
        int gr = b * SEQ + t;          // global row in [B*T, C] layout
        int rt = gr >> 7, rl = gr & 127;
        #pragma unroll
        for (int db = 0; db < 8; db++) {
            int c = h * 64 + db * 8 + cb;      // channel in [0, 384)
            int kb = c >> 5;
            size_t base = (size_t)(rt * NKB + kb) * 8192;
            uint32_t off = sw64((uint32_t)(rl * 64 + (c & 31) * 2));
            float v0 = o[db][rp * 2 + 0] * inv;
            float v1 = o[db][rp * 2 + 1] * inv;
            *(uint32_t*)(g_yh + base + off) = pack_h2(v0, v1);
            *(uint32_t*)(g_yl + base + off) = pack_h2(lo_res(v0), lo_res(v1));
        }
    }
}

// ---------------------------------------------------------------------------
extern "C" void kernel_launch(void* const* d_in, const int* in_sizes, int n_in,
                              void* d_out, int out_size)
{
    const float* x    = (const float*)d_in[0];
    const float* cosp = (const float*)d_in[1];
    const float* sinp = (const float*)d_in[2];
    const int*   tmsk = (const int*)  d_in[3];
    const float* Wq   = (const float*)d_in[4];
    const float* Wk   = (const float*)d_in[5];
    const float* Wv   = (const float*)d_in[6];
    const float* Wpr  = (const float*)d_in[7];
    const float* mbr  = (const float*)d_in[8];
    const int*   bsp  = (const int*)  d_in[9];
    float* out = (float*)d_out;

    cudaFuncSetAttribute(attn_kernel,
                         cudaFuncAttributeMaxDynamicSharedMemorySize, 2 * STAGE_SZ);

    conv_kernel<<<NRT * NKB + 4 * NJT * NKB, 256>>>(x, Wq, Wk, Wv, Wpr);

    dim3 gg(NRT, NJT);   // 64 x 6
    gemm_img<1, 0, 0, true ><<<gg, 256>>>(0, cosp, sinp, nullptr);
    gemm_img<1, 0, 1, true ><<<gg, 256>>>(1, cosp, sinp, nullptr);
    gemm_img<3, 0, 2, false><<<gg, 256>>>(2, nullptr, nullptr, nullptr);

    attn_kernel<<<dim3(SEQ / 128, BATCH * NH), 256, 2 * STAGE_SZ>>>(tmsk, mbr, bsp);

    gemm_img<3, 1, 3, false><<<gg, 256>>>(3, nullptr, nullptr, out);
}

// round 15
// speedup vs baseline: 1.4994x; 1.1890x over previous
#include <cuda_runtime.h>
#include <cuda_fp16.h>
#include <math.h>
#include <stdint.h>

#define BATCH 4
#define SEQ   2048
#define CDIM  384
#define NH    6
#define HD    64
#define NT    (SEQ / 64)            // 32 KV tiles per (b,h)
#define NRX   (BATCH * SEQ)         // 8192 rows of x / y
#define NRT   (NRX / 128)           // 64 row-tiles
#define NKB   (CDIM / 32)           // 12 k-blocks
#define NJT   (CDIM / 64)           // 6 j-tiles per weight matrix

// Scratch (static __device__ arrays; referenced ONLY from device code).
__device__ float g_q[BATCH*NH*SEQ*HD];
// K/V fp16 tile images for attention (sw128, ldmatrix-ready).
__device__ uint4 g_kh[BATCH*NH*NT*512];
__device__ uint4 g_vh[BATCH*NH*NT*512];
// Pre-converted GEMM operand images (sw64, ldsm-ready).
__device__ char g_xh[NRT*NKB*8192];
__device__ char g_xl[NRT*NKB*8192];
__device__ char g_yh[NRT*NKB*8192];
__device__ char g_yl[NRT*NKB*8192];
__device__ char g_wh[4*NJT*NKB*4096];
__device__ char g_wl[4*NJT*NKB*4096];

// ---------------------------------------------------------------------------
// helpers (sm_80-compatible PTX; assembles for sm_100)
// ---------------------------------------------------------------------------
__device__ __forceinline__ uint32_t smem_u32(const void* p) {
    uint32_t a;
    asm("{ .reg .u64 t; cvta.to.shared.u64 t, %1; cvt.u32.u64 %0, t; }"
        : "=r"(a) : "l"(p));
    return a;
}
__device__ __forceinline__ void ldsm_x4(uint32_t& r0, uint32_t& r1,
                                        uint32_t& r2, uint32_t& r3, uint32_t addr) {
    asm volatile("ldmatrix.sync.aligned.m8n8.x4.shared.b16 {%0,%1,%2,%3}, [%4];"
                 : "=r"(r0), "=r"(r1), "=r"(r2), "=r"(r3) : "r"(addr));
}
__device__ __forceinline__ void ldsm_x4_t(uint32_t& r0, uint32_t& r1,
                                          uint32_t& r2, uint32_t& r3, uint32_t addr) {
    asm volatile("ldmatrix.sync.aligned.m8n8.x4.trans.shared.b16 {%0,%1,%2,%3}, [%4];"
                 : "=r"(r0), "=r"(r1), "=r"(r2), "=r"(r3) : "r"(addr));
}
__device__ __forceinline__ void mma16816(float* d,
    uint32_t a0, uint32_t a1, uint32_t a2, uint32_t a3, uint32_t b0, uint32_t b1) {
    asm volatile(
        "mma.sync.aligned.m16n8k16.row.col.f32.f16.f16.f32 "
        "{%0,%1,%2,%3}, {%4,%5,%6,%7}, {%8,%9}, {%0,%1,%2,%3};"
        : "+f"(d[0]), "+f"(d[1]), "+f"(d[2]), "+f"(d[3])
        : "r"(a0), "r"(a1), "r"(a2), "r"(a3), "r"(b0), "r"(b1));
}
__device__ __forceinline__ uint32_t pack_h2(float x, float y) {
    __half2 h = __floats2half2_rn(x, y);
    return *reinterpret_cast<uint32_t*>(&h);
}
__device__ __forceinline__ float lo_res(float x) {
    return x - __half2float(__float2half_rn(x));
}
__device__ __forceinline__ uint32_t sw64(uint32_t off) {
    return off ^ ((off >> 3) & 0x30);
}
__device__ __forceinline__ uint32_t sw128(uint32_t off) {
    return off ^ ((off >> 3) & 0x70);
}
__device__ __forceinline__ void cp_async16(uint32_t dst, const void* src) {
    asm volatile("cp.async.cg.shared.global [%0], [%1], 16;" :: "r"(dst), "l"(src));
}
#define CP_COMMIT() asm volatile("cp.async.commit_group;" ::: "memory")
#define CP_WAIT1()  asm volatile("cp.async.wait_group 1;" ::: "memory")
#define CP_WAIT0()  asm volatile("cp.async.wait_group 0;" ::: "memory")

// ===========================================================================
// Conversion kernel: fp32 -> pre-swizzled fp16 hi/lo tile images.
// ===========================================================================
__global__ __launch_bounds__(256)
void conv_kernel(const float* __restrict__ x,
                 const float* __restrict__ Wq,
                 const float* __restrict__ Wk,
                 const float* __restrict__ Wv,
                 const float* __restrict__ Wp)
{
    const int bid = blockIdx.x;
    const int tid = threadIdx.x;
    if (bid < NRT * NKB) {
        int rt = bid / NKB, kb = bid - rt * NKB;
        int rl = tid >> 1, ko = (tid & 1) * 16;
        const float* src = x + (size_t)(rt * 128 + rl) * CDIM + kb * 32 + ko;
        float4 f0 = *(const float4*)(src + 0);
        float4 f1 = *(const float4*)(src + 4);
        float4 f2 = *(const float4*)(src + 8);
        float4 f3 = *(const float4*)(src + 12);
        uint4 h0, h1, l0, l1;
        h0.x = pack_h2(f0.x, f0.y); h0.y = pack_h2(f0.z, f0.w);
        h0.z = pack_h2(f1.x, f1.y); h0.w = pack_h2(f1.z, f1.w);
        h1.x = pack_h2(f2.x, f2.y); h1.y = pack_h2(f2.z, f2.w);
        h1.z = pack_h2(f3.x, f3.y); h1.w = pack_h2(f3.z, f3.w);
        l0.x = pack_h2(lo_res(f0.x), lo_res(f0.y)); l0.y = pack_h2(lo_res(f0.z), lo_res(f0.w));
        l0.z = pack_h2(lo_res(f1.x), lo_res(f1.y)); l0.w = pack_h2(lo_res(f1.z), lo_res(f1.w));
        l1.x = pack_h2(lo_res(f2.x), lo_res(f2.y)); l1.y = pack_h2(lo_res(f2.z), lo_res(f2.w));
        l1.z = pack_h2(lo_res(f3.x), lo_res(f3.y)); l1.w = pack_h2(lo_res(f3.z), lo_res(f3.w));
        char* dh = g_xh + (size_t)bid * 8192;
        char* dl = g_xl + (size_t)bid * 8192;
        uint32_t g = (uint32_t)(rl * 64 + ko * 2);
        *(uint4*)(dh + sw64(g))      = h0;
        *(uint4*)(dh + sw64(g + 16)) = h1;
        *(uint4*)(dl + sw64(g))      = l0;
        *(uint4*)(dl + sw64(g + 16)) = l1;
    } else {
        int idx = bid - NRT * NKB;
        int mat = idx / (NJT * NKB);
        int r   = idx - mat * (NJT * NKB);
        int jt = r / NKB, kb = r - jt * NKB;
        int rw = tid >> 2, kw = (tid & 3) * 8;
        const float* Wm = (mat == 0) ? Wq : (mat == 1) ? Wk : (mat == 2) ? Wv : Wp;
        const float* src = Wm + (size_t)(jt * 64 + rw) * CDIM + kb * 32 + kw;
        float4 f0 = *(const float4*)(src + 0);
        float4 f1 = *(const float4*)(src + 4);
        uint4 hh, ll;
        hh.x = pack_h2(f0.x, f0.y); hh.y = pack_h2(f0.z, f0.w);
        hh.z = pack_h2(f1.x, f1.y); hh.w = pack_h2(f1.z, f1.w);
        ll.x = pack_h2(lo_res(f0.x), lo_res(f0.y)); ll.y = pack_h2(lo_res(f0.z), lo_res(f0.w));
        ll.z = pack_h2(lo_res(f1.x), lo_res(f1.y)); ll.w = pack_h2(lo_res(f1.z), lo_res(f1.w));
        char* dh = g_wh + (size_t)idx * 4096;
        char* dl = g_wl + (size_t)idx * 4096;
        uint32_t g = (uint32_t)(rw * 64 + kw * 2);
        *(uint4*)(dh + sw64(g)) = hh;
        *(uint4*)(dl + sw64(g)) = ll;
    }
}

// ===========================================================================
// Image-fed GEMM: pure cp.async (double-buffered) + ldsm + mma.
//   DST == -1: fused q/k — blockIdx.z selects mat (0=Wq->g_q, 1=Wk->g_kh).
//   SPLIT 1: A-hi * W-hi.  SPLIT 3: hh + lh + hl (~fp32).
// ===========================================================================
template<int SPLIT, int ASRC, int DST, bool ROPE>
__global__ __launch_bounds__(256)
void gemm_img(int mat,
              const float* __restrict__ cosp, const float* __restrict__ sinp,
              float* __restrict__ outp)
{
    constexpr int OFF_ALO = 8192;
    constexpr int OFF_WHI = (SPLIT == 3) ? 16384 : 8192;
    constexpr int OFF_WLO = 20480;
    constexpr int STG     = (SPLIT == 3) ? 24576 : 12288;
    __shared__ __align__(16) char sbuf[2 * STG];

    const int tid  = threadIdx.x;
    const int w    = tid >> 5;
    const int lane = tid & 31;
    const int rt   = blockIdx.x;
    const int jt   = blockIdx.y;
    const int zsel = (DST == -1) ? (int)blockIdx.z : 0;
    const int matv = (DST == -1) ? zsel : mat;

    const char* Ahi = (ASRC ? g_yh : g_xh) + (size_t)(rt * NKB) * 8192;
    const char* Alo = (ASRC ? g_yl : g_xl) + (size_t)(rt * NKB) * 8192;
    const char* Whi = g_wh + (size_t)((matv * NJT + jt) * NKB) * 4096;
    const char* Wlo = g_wl + (size_t)((matv * NJT + jt) * NKB) * 4096;

    const uint32_t sbA = smem_u32(sbuf);

    float acc[8][4];
    #pragma unroll
    for (int m = 0; m < 8; m++)
        #pragma unroll
        for (int i = 0; i < 4; i++) acc[m][i] = 0.0f;

    const uint32_t aoff = (uint32_t)((w * 16 + (lane & 15)) * 64 + ((lane >> 4) & 1) * 16);
    const int joK = (lane & 7) + ((lane >> 4) & 1) * 8;
    const int doK = ((lane >> 3) & 1) * 8;

    {
        uint32_t sb = sbA;
        cp_async16(sb + tid * 16,           Ahi + tid * 16);
        cp_async16(sb + 4096 + tid * 16,    Ahi + 4096 + tid * 16);
        cp_async16(sb + OFF_WHI + tid * 16, Whi + tid * 16);
        if (SPLIT == 3) {
            cp_async16(sb + OFF_ALO + tid * 16,        Alo + tid * 16);
            cp_async16(sb + OFF_ALO + 4096 + tid * 16, Alo + 4096 + tid * 16);
            cp_async16(sb + OFF_WLO + tid * 16,        Wlo + tid * 16);
        }
        CP_COMMIT();
    }

    for (int kb = 0; kb < NKB; kb++) {
        const int s = kb & 1;
        if (kb + 1 < NKB) {
            uint32_t sb = sbA + (s ^ 1) * STG;
            size_t ao = (size_t)(kb + 1) * 8192;
            size_t wo = (size_t)(kb + 1) * 4096;
            cp_async16(sb + tid * 16,           Ahi + ao + tid * 16);
            cp_async16(sb + 4096 + tid * 16,    Ahi + ao + 4096 + tid * 16);
            cp_async16(sb + OFF_WHI + tid * 16, Whi + wo + tid * 16);
            if (SPLIT == 3) {
                cp_async16(sb + OFF_ALO + tid * 16,        Alo + ao + tid * 16);
                cp_async16(sb + OFF_ALO + 4096 + tid * 16, Alo + ao + 4096 + tid * 16);
                cp_async16(sb + OFF_WLO + tid * 16,        Wlo + wo + tid * 16);
            }
            CP_COMMIT();
            CP_WAIT1();
        } else {
            CP_WAIT0();
        }
        __syncthreads();

        const uint32_t aHi = sbA + s * STG;
        const uint32_t aLo = aHi + OFF_ALO;
        const uint32_t wHi = aHi + OFF_WHI;
        const uint32_t wLo = aHi + OFF_WLO;

        #pragma unroll
        for (int kc = 0; kc < 2; kc++) {
            uint32_t ah0, ah1, ah2, ah3;
            ldsm_x4(ah0, ah1, ah2, ah3, aHi + sw64(aoff + kc * 32));
            uint32_t al0, al1, al2, al3;
            if (SPLIT == 3)
                ldsm_x4(al0, al1, al2, al3, aLo + sw64(aoff + kc * 32));
            #pragma unroll
            for (int cg = 0; cg < 4; cg++) {
                uint32_t boff = sw64((uint32_t)((cg * 16 + joK) * 64 + kc * 32 + doK * 2));
                uint32_t bh0, bh1, bh2, bh3;
                ldsm_x4(bh0, bh1, bh2, bh3, wHi + boff);
                mma16816(acc[2*cg],   ah0, ah1, ah2, ah3, bh0, bh1);
                mma16816(acc[2*cg+1], ah0, ah1, ah2, ah3, bh2, bh3);
                if (SPLIT == 3) {
                    mma16816(acc[2*cg],   al0, al1, al2, al3, bh0, bh1);
                    mma16816(acc[2*cg+1], al0, al1, al2, al3, bh2, bh3);
                    uint32_t bl0, bl1, bl2, bl3;
                    ldsm_x4(bl0, bl1, bl2, bl3, wLo + boff);
                    mma16816(acc[2*cg],   ah0, ah1, ah2, ah3, bl0, bl1);
                    mma16816(acc[2*cg+1], ah0, ah1, ah2, ah3, bl2, bl3);
                }
            }
        }
        __syncthreads();
    }

    // ---- epilogue ----
    const int rbase = rt * 128;
    const int jb    = jt * 64;
    const int rA = rbase + w * 16 + (lane >> 2);
    const int cb = (lane & 3) * 2;

    #pragma unroll
    for (int rp = 0; rp < 2; rp++) {
        int r = rA + rp * 8;
        int i0 = rp * 2;
        if (ROPE) {
            int t = r & (SEQ - 1);
            #pragma unroll
            for (int m = 0; m < 4; m++) {
                int d0 = (m >> 1) * 16 + (m & 1) * 8 + cb;
                float c0 = cosp[t * 32 + d0],     s0 = sinp[t * 32 + d0];
                float c1 = cosp[t * 32 + d0 + 1], s1 = sinp[t * 32 + d0 + 1];
                float x1 = acc[m][i0],     x2 = acc[m+4][i0];
                acc[m][i0]     =  x1 * c0 + x2 * s0;
                acc[m+4][i0]   = -x1 * s0 + x2 * c0;
                float y1 = acc[m][i0+1],   y2 = acc[m+4][i0+1];
                acc[m][i0+1]   =  y1 * c1 + y2 * s1;
                acc[m+4][i0+1] = -y1 * s1 + y2 * c1;
            }
            float ss = 0.0f;
            #pragma unroll
            for (int m = 0; m < 8; m++)
                ss += acc[m][i0]*acc[m][i0] + acc[m][i0+1]*acc[m][i0+1];
            ss += __shfl_xor_sync(0xffffffffu, ss, 1);
            ss += __shfl_xor_sync(0xffffffffu, ss, 2);
            float rn = rsqrtf(ss * (1.0f / HD) + 1.1920929e-07f);
            #pragma unroll
            for (int m = 0; m < 8; m++) { acc[m][i0] *= rn; acc[m][i0+1] *= rn; }
        }
        if (DST == 3) {
            float* o = outp + (size_t)r * CDIM + jb;
            #pragma unroll
            for (int m = 0; m < 8; m++) {
                int d0 = (m >> 1) * 16 + (m & 1) * 8 + cb;
                *(float2*)(o + d0) = make_float2(acc[m][i0], acc[m][i0+1]);
            }
        } else if (DST == -1 && zsel == 0) {
            int bb = r >> 11, t = r & (SEQ - 1);
            float* o = g_q + ((size_t)(bb * NH + jt) * SEQ + t) * HD;
            #pragma unroll
            for (int m = 0; m < 8; m++) {
                int d0 = (m >> 1) * 16 + (m & 1) * 8 + cb;
                *(float2*)(o + d0) = make_float2(acc[m][i0], acc[m][i0+1]);
            }
        } else {
            // K (zsel==1) or V (DST==2): fp16 pre-swizzled tile images
            int bb = r >> 11, t = r & (SEQ - 1);
            int bh = bb * NH + jt;
            int tile = t >> 6, j = t & 63;
            size_t base = ((size_t)(bh * NT + tile)) * 8192;
            char* dh = (char*)((DST == 2) ? g_vh : g_kh) + base;
            #pragma unroll
            for (int m = 0; m < 8; m++) {
                int d0 = (m >> 1) * 16 + (m & 1) * 8 + cb;
                uint32_t off = sw128((uint32_t)(j * 128 + d0 * 2));
                *(uint32_t*)(dh + off) = pack_h2(acc[m][i0], acc[m][i0+1]);
            }
        }
    }
}

// ===========================================================================
// Flash attention: full KV loop, __expf, -4 shift. P single fp16 (no lo split
// — P rounding ~1.4e-4 rms on positive weights, inside error budget).
// Epilogue writes y as fp16 hi/lo sw64 images for the proj GEMM.
//   Stage (16640 B): Khi[8192] Vhi[8192] mask[256]
// ===========================================================================
#define STAGE_SZ 16640

__global__ __launch_bounds__(256, 2)
void attn_kernel(const int* __restrict__ tmask,
                 const float* __restrict__ mb_raw,
                 const int* __restrict__ bsp)
{
    extern __shared__ __align__(16) char s_dyn[];

    const int tid  = threadIdx.x;
    const int w    = tid >> 5;
    const int lane = tid & 31;
    const int bh   = blockIdx.y;
    const int b    = bh / NH;
    const int h    = bh - b * NH;
    const int qb   = blockIdx.x * 128;

    const float* Qg = g_q + (size_t)bh * SEQ * HD;
    const char*  KH = (const char*)g_kh + (size_t)bh * NT * 8192;
    const char*  VH = (const char*)g_vh + (size_t)bh * NT * 8192;
    const int*   MK = tmask + b * SEQ;

    const uint32_t sb0 = smem_u32(s_dyn);

    float bs;
    {
        int iv = bsp[0];
        bs = (iv > -1000000 && iv < 1000000) ? (float)iv : __int_as_float(iv);
    }
    float G1 = 0.5f * tanhf(mb_raw[h * 3 + 0]) * bs;
    float G2 = 0.5f * tanhf(mb_raw[h * 3 + 1]) * bs;
    float G3 = 0.5f * tanhf(mb_raw[h * 3 + 2]) * bs;
    const float b01 = fminf(2.0f, fmaxf(-2.0f, G2));
    const float b10 = fminf(2.0f, fmaxf(-2.0f, G1));
    const float b11 = fminf(2.0f, fmaxf(-2.0f, G1 + G2 + G3));

    const int rA = qb + w * 16 + (lane >> 2);
    const int cb = (lane & 3) * 2;
    const int miA = MK[rA];
    const int miB = MK[rA + 8];
    const float bm0A = (miA ? b10 : 0.0f) - 4.0f;
    const float bm1A = (miA ? b11 : b01 ) - 4.0f;
    const float bm0B = (miB ? b10 : 0.0f) - 4.0f;
    const float bm1B = (miB ? b11 : b01 ) - 4.0f;

    uint32_t qhi[16];
    {
        const float* qA = Qg + (size_t)rA * HD + cb;
        const float* qB = qA + 8 * HD;
        #pragma unroll
        for (int kc = 0; kc < 4; kc++) {
            float2 fA0 = *(const float2*)(qA + kc * 16);
            float2 fB0 = *(const float2*)(qB + kc * 16);
            float2 fA1 = *(const float2*)(qA + kc * 16 + 8);
            float2 fB1 = *(const float2*)(qB + kc * 16 + 8);
            qhi[kc*4+0] = pack_h2(fA0.x, fA0.y);
            qhi[kc*4+1] = pack_h2(fB0.x, fB0.y);
            qhi[kc*4+2] = pack_h2(fA1.x, fA1.y);
            qhi[kc*4+3] = pack_h2(fB1.x, fB1.y);
        }
    }

    const int joK = (lane & 7) + ((lane >> 4) & 1) * 8;
    const int doK = ((lane >> 3) & 1) * 8;
    const uint32_t lK = (uint32_t)(joK * 128 + doK * 2);
    const uint32_t xK = (uint32_t)((joK & 7) << 4);
    const int joV = (lane & 7) + ((lane >> 3) & 1) * 8;
    const int doV = ((lane >> 4) & 1) * 8;
    const uint32_t lV = (uint32_t)(joV * 128 + doV * 2);
    const uint32_t xV = (uint32_t)((joV & 7) << 4);

    float o[8][4];
    #pragma unroll
    for (int i = 0; i < 8; i++)
        #pragma unroll
        for (int jx = 0; jx < 4; jx++) o[i][jx] = 0.0f;
    float lA = 0.0f, lB = 0.0f;

    {
        uint32_t sb = sb0;
        #pragma unroll
        for (int i = 0; i < 2; i++) {
            uint32_t c = (uint32_t)tid * 16 + i * 4096;
            cp_async16(sb + c,        KH + c);
            cp_async16(sb + 8192 + c, VH + c);
        }
        if (tid < 16) cp_async16(sb + 16384 + tid * 16, MK + tid * 4);
        CP_COMMIT();
    }

    for (int kt = 0; kt < NT; kt++) {
        const int s = kt & 1;
        if (kt + 1 < NT) {
            uint32_t sb = sb0 + (s ^ 1) * STAGE_SZ;
            size_t toff = (size_t)(kt + 1) * 8192;
            #pragma unroll
            for (int i = 0; i < 2; i++) {
                uint32_t c = (uint32_t)tid * 16 + i * 4096;
                cp_async16(sb + c,        KH + toff + c);
                cp_async16(sb + 8192 + c, VH + toff + c);
            }
            if (tid < 16) cp_async16(sb + 16384 + tid * 16, MK + (kt + 1) * 64 + tid * 4);
            CP_COMMIT();
            CP_WAIT1();
        } else {
            CP_WAIT0();
        }
        __syncthreads();

        const uint32_t khiA = sb0 + s * STAGE_SZ;
        const uint32_t vhiA = khiA + 8192;
        const int* mjs = (const int*)(s_dyn + s * STAGE_SZ + 16384);

        #pragma unroll
        for (int half = 0; half < 2; half++) {
            float sf[4][4];
            #pragma unroll
            for (int i = 0; i < 4; i++)
                #pragma unroll
                for (int jx = 0; jx < 4; jx++) sf[i][jx] = 0.0f;

            #pragma unroll
            for (int nb2 = 0; nb2 < 2; nb2++) {
                #pragma unroll
                for (int kc = 0; kc < 4; kc++) {
                    uint32_t off = (uint32_t)((half * 2 + nb2) * 2048 + kc * 32) + lK;
                    uint32_t bh0, bh1, bh2, bh3;
                    ldsm_x4(bh0, bh1, bh2, bh3, (khiA + off) ^ xK);
                    mma16816(sf[2*nb2],   qhi[kc*4+0], qhi[kc*4+1], qhi[kc*4+2], qhi[kc*4+3], bh0, bh1);
                    mma16816(sf[2*nb2+1], qhi[kc*4+0], qhi[kc*4+1], qhi[kc*4+2], qhi[kc*4+3], bh2, bh3);
                }
            }

            uint32_t phi[8];
            #pragma unroll
            for (int nb = 0; nb < 4; nb++) {
                int j0 = half * 32 + nb * 8 + cb;
                int mj0 = mjs[j0], mj1 = mjs[j0 + 1];
                float bA0 = mj0 ? bm1A : bm0A;
                float bA1 = mj1 ? bm1A : bm0A;
                float bB0 = mj0 ? bm1B : bm0B;
                float bB1 = mj1 ? bm1B : bm0B;
                float pA0 = __expf(fmaf(sf[nb][0], 0.125f, bA0));
                float pA1 = __expf(fmaf(sf[nb][1], 0.125f, bA1));
                float pB0 = __expf(fmaf(sf[nb][2], 0.125f, bB0));
                float pB1 = __expf(fmaf(sf[nb][3], 0.125f, bB1));
                lA += pA0 + pA1;
                lB += pB0 + pB1;
                phi[nb*2+0] = pack_h2(pA0, pA1);
                phi[nb*2+1] = pack_h2(pB0, pB1);
            }

            #pragma unroll
            for (int db2 = 0; db2 < 4; db2++) {
                #pragma unroll
                for (int kc = 0; kc < 2; kc++) {
                    uint32_t off = (uint32_t)((half * 2 + kc) * 2048 + db2 * 32) + lV;
                    uint32_t v0, v1, v2, v3;
                    ldsm_x4_t(v0, v1, v2, v3, (vhiA + off) ^ xV);
                    mma16816(o[2*db2],   phi[4*kc+0], phi[4*kc+1], phi[4*kc+2], phi[4*kc+3], v0, v1);
                    mma16816(o[2*db2+1], phi[4*kc+0], phi[4*kc+1], phi[4*kc+2], phi[4*kc+3], v2, v3);
                }
            }
        }
        __syncthreads();
    }

    // ---- epilogue: normalize and write fp16 hi/lo y-images ----
    lA += __shfl_xor_sync(0xffffffffu, lA, 1);
    lA += __shfl_xor_sync(0xffffffffu, lA, 2);
    lB += __shfl_xor_sync(0xffffffffu, lB, 1);
    lB += __shfl_xor_sync(0xffffffffu, lB, 2);
    float iA = 1.0f / lA, iB = 1.0f / lB;

    #pragma unroll
    for (int rp = 0; rp < 2; rp++) {
        int t = rA + rp * 8;
        float inv = rp ? iB : iA;
        int gr = b * SEQ + t;
        int rt = gr >> 7, rl = gr & 127;
        #pragma unroll
        for (int db = 0; db < 8; db++) {
            int c = h * 64 + db * 8 + cb;
            int kb = c >> 5;
            size_t base = (size_t)(rt * NKB + kb) * 8192;
            uint32_t off = sw64((uint32_t)(rl * 64 + (c & 31) * 2));
            float v0 = o[db][rp * 2 + 0] * inv;
            float v1 = o[db][rp * 2 + 1] * inv;
            *(uint32_t*)(g_yh + base + off) = pack_h2(v0, v1);
            *(uint32_t*)(g_yl + base + off) = pack_h2(lo_res(v0), lo_res(v1));
        }
    }
}

// ---------------------------------------------------------------------------
extern "C" void kernel_launch(void* const* d_in, const int* in_sizes, int n_in,
                              void* d_out, int out_size)
{
    const float* x    = (const float*)d_in[0];
    const float* cosp = (const float*)d_in[1];
    const float* sinp = (const float*)d_in[2];
    const int*   tmsk = (const int*)  d_in[3];
    const float* Wq   = (const float*)d_in[4];
    const float* Wk   = (const float*)d_in[5];
    const float* Wv   = (const float*)d_in[6];
    const float* Wpr  = (const float*)d_in[7];
    const float* mbr  = (const float*)d_in[8];
    const int*   bsp  = (const int*)  d_in[9];
    float* out = (float*)d_out;

    cudaFuncSetAttribute(attn_kernel,
                         cudaFuncAttributeMaxDynamicSharedMemorySize, 2 * STAGE_SZ);

    conv_kernel<<<NRT * NKB + 4 * NJT * NKB, 256>>>(x, Wq, Wk, Wv, Wpr);

    gemm_img<1, 0, -1, true ><<<dim3(NRT, NJT, 2), 256>>>(0, cosp, sinp, nullptr);
    gemm_img<3, 0,  2, false><<<dim3(NRT, NJT),    256>>>(2, nullptr, nullptr, nullptr);

    attn_kernel<<<dim3(SEQ / 128, BATCH * NH), 256, 2 * STAGE_SZ>>>(tmsk, mbr, bsp);

    gemm_img<3, 1,  3, false><<<dim3(NRT, NJT),    256>>>(3, nullptr, nullptr, out);
}

// round 16
// speedup vs baseline: 1.5213x; 1.0146x over previous
#include <cuda_runtime.h>
#include <cuda_fp16.h>
#include <math.h>
#include <stdint.h>

#define BATCH 4
#define SEQ   2048
#define CDIM  384
#define NH    6
#define HD    64
#define NT    (SEQ / 64)            // 32 KV tiles per (b,h)
#define NTP   (NT / 2)              // 16 KV tile-PAIRS per (b,h)
#define NRX   (BATCH * SEQ)         // 8192 rows of x / y
#define NRT   (NRX / 128)           // 64 row-tiles
#define NKB   (CDIM / 32)           // 12 k-blocks
#define NJT   (CDIM / 64)           // 6 j-tiles per weight matrix

// Scratch (static __device__ arrays; referenced ONLY from device code).
__device__ float g_q[BATCH*NH*SEQ*HD];
// K/V fp16 tile images for attention (sw128, ldmatrix-ready).
__device__ uint4 g_kh[BATCH*NH*NT*512];
__device__ uint4 g_vh[BATCH*NH*NT*512];
// Pre-converted GEMM operand images (sw64, ldsm-ready).
__device__ char g_xh[NRT*NKB*8192];
__device__ char g_xl[NRT*NKB*8192];
__device__ char g_yh[NRT*NKB*8192];
__device__ char g_yl[NRT*NKB*8192];
__device__ char g_wh[4*NJT*NKB*4096];
__device__ char g_wl[4*NJT*NKB*4096];

// ---------------------------------------------------------------------------
// helpers (sm_80-compatible PTX; assembles for sm_100)
// ---------------------------------------------------------------------------
__device__ __forceinline__ uint32_t smem_u32(const void* p) {
    uint32_t a;
    asm("{ .reg .u64 t; cvta.to.shared.u64 t, %1; cvt.u32.u64 %0, t; }"
        : "=r"(a) : "l"(p));
    return a;
}
__device__ __forceinline__ void ldsm_x4(uint32_t& r0, uint32_t& r1,
                                        uint32_t& r2, uint32_t& r3, uint32_t addr) {
    asm volatile("ldmatrix.sync.aligned.m8n8.x4.shared.b16 {%0,%1,%2,%3}, [%4];"
                 : "=r"(r0), "=r"(r1), "=r"(r2), "=r"(r3) : "r"(addr));
}
__device__ __forceinline__ void ldsm_x4_t(uint32_t& r0, uint32_t& r1,
                                          uint32_t& r2, uint32_t& r3, uint32_t addr) {
    asm volatile("ldmatrix.sync.aligned.m8n8.x4.trans.shared.b16 {%0,%1,%2,%3}, [%4];"
                 : "=r"(r0), "=r"(r1), "=r"(r2), "=r"(r3) : "r"(addr));
}
__device__ __forceinline__ void mma16816(float* d,
    uint32_t a0, uint32_t a1, uint32_t a2, uint32_t a3, uint32_t b0, uint32_t b1) {
    asm volatile(
        "mma.sync.aligned.m16n8k16.row.col.f32.f16.f16.f32 "
        "{%0,%1,%2,%3}, {%4,%5,%6,%7}, {%8,%9}, {%0,%1,%2,%3};"
        : "+f"(d[0]), "+f"(d[1]), "+f"(d[2]), "+f"(d[3])
        : "r"(a0), "r"(a1), "r"(a2), "r"(a3), "r"(b0), "r"(b1));
}
__device__ __forceinline__ uint32_t pack_h2(float x, float y) {
    __half2 h = __floats2half2_rn(x, y);
    return *reinterpret_cast<uint32_t*>(&h);
}
__device__ __forceinline__ float lo_res(float x) {
    return x - __half2float(__float2half_rn(x));
}
__device__ __forceinline__ uint32_t sw64(uint32_t off) {
    return off ^ ((off >> 3) & 0x30);
}
__device__ __forceinline__ uint32_t sw128(uint32_t off) {
    return off ^ ((off >> 3) & 0x70);
}
__device__ __forceinline__ void cp_async16(uint32_t dst, const void* src) {
    asm volatile("cp.async.cg.shared.global [%0], [%1], 16;" :: "r"(dst), "l"(src));
}
#define CP_COMMIT() asm volatile("cp.async.commit_group;" ::: "memory")
#define CP_WAIT1()  asm volatile("cp.async.wait_group 1;" ::: "memory")
#define CP_WAIT0()  asm volatile("cp.async.wait_group 0;" ::: "memory")

#define L2E 1.44269504088896f

// ===========================================================================
// Conversion kernel: fp32 -> pre-swizzled fp16 hi/lo tile images.
// ===========================================================================
__global__ __launch_bounds__(256)
void conv_kernel(const float* __restrict__ x,
                 const float* __restrict__ Wq,
                 const float* __restrict__ Wk,
                 const float* __restrict__ Wv,
                 const float* __restrict__ Wp)
{
    const int bid = blockIdx.x;
    const int tid = threadIdx.x;
    if (bid < NRT * NKB) {
        int rt = bid / NKB, kb = bid - rt * NKB;
        int rl = tid >> 1, ko = (tid & 1) * 16;
        const float* src = x + (size_t)(rt * 128 + rl) * CDIM + kb * 32 + ko;
        float4 f0 = *(const float4*)(src + 0);
        float4 f1 = *(const float4*)(src + 4);
        float4 f2 = *(const float4*)(src + 8);
        float4 f3 = *(const float4*)(src + 12);
        uint4 h0, h1, l0, l1;
        h0.x = pack_h2(f0.x, f0.y); h0.y = pack_h2(f0.z, f0.w);
        h0.z = pack_h2(f1.x, f1.y); h0.w = pack_h2(f1.z, f1.w);
        h1.x = pack_h2(f2.x, f2.y); h1.y = pack_h2(f2.z, f2.w);
        h1.z = pack_h2(f3.x, f3.y); h1.w = pack_h2(f3.z, f3.w);
        l0.x = pack_h2(lo_res(f0.x), lo_res(f0.y)); l0.y = pack_h2(lo_res(f0.z), lo_res(f0.w));
        l0.z = pack_h2(lo_res(f1.x), lo_res(f1.y)); l0.w = pack_h2(lo_res(f1.z), lo_res(f1.w));
        l1.x = pack_h2(lo_res(f2.x), lo_res(f2.y)); l1.y = pack_h2(lo_res(f2.z), lo_res(f2.w));
        l1.z = pack_h2(lo_res(f3.x), lo_res(f3.y)); l1.w = pack_h2(lo_res(f3.z), lo_res(f3.w));
        char* dh = g_xh + (size_t)bid * 8192;
        char* dl = g_xl + (size_t)bid * 8192;
        uint32_t g = (uint32_t)(rl * 64 + ko * 2);
        *(uint4*)(dh + sw64(g))      = h0;
        *(uint4*)(dh + sw64(g + 16)) = h1;
        *(uint4*)(dl + sw64(g))      = l0;
        *(uint4*)(dl + sw64(g + 16)) = l1;
    } else {
        int idx = bid - NRT * NKB;
        int mat = idx / (NJT * NKB);
        int r   = idx - mat * (NJT * NKB);
        int jt = r / NKB, kb = r - jt * NKB;
        int rw = tid >> 2, kw = (tid & 3) * 8;
        const float* Wm = (mat == 0) ? Wq : (mat == 1) ? Wk : (mat == 2) ? Wv : Wp;
        const float* src = Wm + (size_t)(jt * 64 + rw) * CDIM + kb * 32 + kw;
        float4 f0 = *(const float4*)(src + 0);
        float4 f1 = *(const float4*)(src + 4);
        uint4 hh, ll;
        hh.x = pack_h2(f0.x, f0.y); hh.y = pack_h2(f0.z, f0.w);
        hh.z = pack_h2(f1.x, f1.y); hh.w = pack_h2(f1.z, f1.w);
        ll.x = pack_h2(lo_res(f0.x), lo_res(f0.y)); ll.y = pack_h2(lo_res(f0.z), lo_res(f0.w));
        ll.z = pack_h2(lo_res(f1.x), lo_res(f1.y)); ll.w = pack_h2(lo_res(f1.z), lo_res(f1.w));
        char* dh = g_wh + (size_t)idx * 4096;
        char* dl = g_wl + (size_t)idx * 4096;
        uint32_t g = (uint32_t)(rw * 64 + kw * 2);
        *(uint4*)(dh + sw64(g)) = hh;
        *(uint4*)(dl + sw64(g)) = ll;
    }
}

// ===========================================================================
// Image-fed GEMM: pure cp.async (double-buffered) + ldsm + mma.
//   DST == -1: fused q/k — blockIdx.z selects mat (0=Wq->g_q, 1=Wk->g_kh).
//   SPLIT 1: A-hi * W-hi.  SPLIT 3: hh + lh + hl (~fp32).
// ===========================================================================
template<int SPLIT, int ASRC, int DST, bool ROPE>
__global__ __launch_bounds__(256)
void gemm_img(int mat,
              const float* __restrict__ cosp, const float* __restrict__ sinp,
              float* __restrict__ outp)
{
    constexpr int OFF_ALO = 8192;
    constexpr int OFF_WHI = (SPLIT == 3) ? 16384 : 8192;
    constexpr int OFF_WLO = 20480;
    constexpr int STG     = (SPLIT == 3) ? 24576 : 12288;
    __shared__ __align__(16) char sbuf[2 * STG];

    const int tid  = threadIdx.x;
    const int w    = tid >> 5;
    const int lane = tid & 31;
    const int rt   = blockIdx.x;
    const int jt   = blockIdx.y;
    const int zsel = (DST == -1) ? (int)blockIdx.z : 0;
    const int matv = (DST == -1) ? zsel : mat;

    const char* Ahi = (ASRC ? g_yh : g_xh) + (size_t)(rt * NKB) * 8192;
    const char* Alo = (ASRC ? g_yl : g_xl) + (size_t)(rt * NKB) * 8192;
    const char* Whi = g_wh + (size_t)((matv * NJT + jt) * NKB) * 4096;
    const char* Wlo = g_wl + (size_t)((matv * NJT + jt) * NKB) * 4096;

    const uint32_t sbA = smem_u32(sbuf);

    float acc[8][4];
    #pragma unroll
    for (int m = 0; m < 8; m++)
        #pragma unroll
        for (int i = 0; i < 4; i++) acc[m][i] = 0.0f;

    const uint32_t aoff = (uint32_t)((w * 16 + (lane & 15)) * 64 + ((lane >> 4) & 1) * 16);
    const int joK = (lane & 7) + ((lane >> 4) & 1) * 8;
    const int doK = ((lane >> 3) & 1) * 8;

    {
        uint32_t sb = sbA;
        cp_async16(sb + tid * 16,           Ahi + tid * 16);
        cp_async16(sb + 4096 + tid * 16,    Ahi + 4096 + tid * 16);
        cp_async16(sb + OFF_WHI + tid * 16, Whi + tid * 16);
        if (SPLIT == 3) {
            cp_async16(sb + OFF_ALO + tid * 16,        Alo + tid * 16);
            cp_async16(sb + OFF_ALO + 4096 + tid * 16, Alo + 4096 + tid * 16);
            cp_async16(sb + OFF_WLO + tid * 16,        Wlo + tid * 16);
        }
        CP_COMMIT();
    }

    for (int kb = 0; kb < NKB; kb++) {
        const int s = kb & 1;
        if (kb + 1 < NKB) {
            uint32_t sb = sbA + (s ^ 1) * STG;
            size_t ao = (size_t)(kb + 1) * 8192;
            size_t wo = (size_t)(kb + 1) * 4096;
            cp_async16(sb + tid * 16,           Ahi + ao + tid * 16);
            cp_async16(sb + 4096 + tid * 16,    Ahi + ao + 4096 + tid * 16);
            cp_async16(sb + OFF_WHI + tid * 16, Whi + wo + tid * 16);
            if (SPLIT == 3) {
                cp_async16(sb + OFF_ALO + tid * 16,        Alo + ao + tid * 16);
                cp_async16(sb + OFF_ALO + 4096 + tid * 16, Alo + ao + 4096 + tid * 16);
                cp_async16(sb + OFF_WLO + tid * 16,        Wlo + wo + tid * 16);
            }
            CP_COMMIT();
            CP_WAIT1();
        } else {
            CP_WAIT0();
        }
        __syncthreads();

        const uint32_t aHi = sbA + s * STG;
        const uint32_t aLo = aHi + OFF_ALO;
        const uint32_t wHi = aHi + OFF_WHI;
        const uint32_t wLo = aHi + OFF_WLO;

        #pragma unroll
        for (int kc = 0; kc < 2; kc++) {
            uint32_t ah0, ah1, ah2, ah3;
            ldsm_x4(ah0, ah1, ah2, ah3, aHi + sw64(aoff + kc * 32));
            uint32_t al0, al1, al2, al3;
            if (SPLIT == 3)
                ldsm_x4(al0, al1, al2, al3, aLo + sw64(aoff + kc * 32));
            #pragma unroll
            for (int cg = 0; cg < 4; cg++) {
                uint32_t boff = sw64((uint32_t)((cg * 16 + joK) * 64 + kc * 32 + doK * 2));
                uint32_t bh0, bh1, bh2, bh3;
                ldsm_x4(bh0, bh1, bh2, bh3, wHi + boff);
                mma16816(acc[2*cg],   ah0, ah1, ah2, ah3, bh0, bh1);
                mma16816(acc[2*cg+1], ah0, ah1, ah2, ah3, bh2, bh3);
                if (SPLIT == 3) {
                    mma16816(acc[2*cg],   al0, al1, al2, al3, bh0, bh1);
                    mma16816(acc[2*cg+1], al0, al1, al2, al3, bh2, bh3);
                    uint32_t bl0, bl1, bl2, bl3;
                    ldsm_x4(bl0, bl1, bl2, bl3, wLo + boff);
                    mma16816(acc[2*cg],   ah0, ah1, ah2, ah3, bl0, bl1);
                    mma16816(acc[2*cg+1], ah0, ah1, ah2, ah3, bl2, bl3);
                }
            }
        }
        __syncthreads();
    }

    // ---- epilogue ----
    const int rbase = rt * 128;
    const int jb    = jt * 64;
    const int rA = rbase + w * 16 + (lane >> 2);
    const int cb = (lane & 3) * 2;

    #pragma unroll
    for (int rp = 0; rp < 2; rp++) {
        int r = rA + rp * 8;
        int i0 = rp * 2;
        if (ROPE) {
            int t = r & (SEQ - 1);
            #pragma unroll
            for (int m = 0; m < 4; m++) {
                int d0 = (m >> 1) * 16 + (m & 1) * 8 + cb;
                float c0 = cosp[t * 32 + d0],     s0 = sinp[t * 32 + d0];
                float c1 = cosp[t * 32 + d0 + 1], s1 = sinp[t * 32 + d0 + 1];
                float x1 = acc[m][i0],     x2 = acc[m+4][i0];
                acc[m][i0]     =  x1 * c0 + x2 * s0;
                acc[m+4][i0]   = -x1 * s0 + x2 * c0;
                float y1 = acc[m][i0+1],   y2 = acc[m+4][i0+1];
                acc[m][i0+1]   =  y1 * c1 + y2 * s1;
                acc[m+4][i0+1] = -y1 * s1 + y2 * c1;
            }
            float ss = 0.0f;
            #pragma unroll
            for (int m = 0; m < 8; m++)
                ss += acc[m][i0]*acc[m][i0] + acc[m][i0+1]*acc[m][i0+1];
            ss += __shfl_xor_sync(0xffffffffu, ss, 1);
            ss += __shfl_xor_sync(0xffffffffu, ss, 2);
            float rn = rsqrtf(ss * (1.0f / HD) + 1.1920929e-07f);
            #pragma unroll
            for (int m = 0; m < 8; m++) { acc[m][i0] *= rn; acc[m][i0+1] *= rn; }
        }
        if (DST == 3) {
            float* o = outp + (size_t)r * CDIM + jb;
            #pragma unroll
            for (int m = 0; m < 8; m++) {
                int d0 = (m >> 1) * 16 + (m & 1) * 8 + cb;
                *(float2*)(o + d0) = make_float2(acc[m][i0], acc[m][i0+1]);
            }
        } else if (DST == -1 && zsel == 0) {
            int bb = r >> 11, t = r & (SEQ - 1);
            float* o = g_q + ((size_t)(bb * NH + jt) * SEQ + t) * HD;
            #pragma unroll
            for (int m = 0; m < 8; m++) {
                int d0 = (m >> 1) * 16 + (m & 1) * 8 + cb;
                *(float2*)(o + d0) = make_float2(acc[m][i0], acc[m][i0+1]);
            }
        } else {
            // K (zsel==1) or V (DST==2): fp16 pre-swizzled tile images
            int bb = r >> 11, t = r & (SEQ - 1);
            int bh = bb * NH + jt;
            int tile = t >> 6, j = t & 63;
            size_t base = ((size_t)(bh * NT + tile)) * 8192;
            char* dh = (char*)((DST == 2) ? g_vh : g_kh) + base;
            #pragma unroll
            for (int m = 0; m < 8; m++) {
                int d0 = (m >> 1) * 16 + (m & 1) * 8 + cb;
                uint32_t off = sw128((uint32_t)(j * 128 + d0 * 2));
                *(uint32_t*)(dh + off) = pack_h2(acc[m][i0], acc[m][i0+1]);
            }
        }
    }
}

// ===========================================================================
// Flash attention: KV mega-stage of TWO 64-row tiles per cp.async stage
// (halves sync/commit count). P single fp16; exp2-folded softmax; -4 shift.
// Epilogue writes y as fp16 hi/lo sw64 images for the proj GEMM.
//   Stage (33280 B): Khi[16384] Vhi[16384] mask[512]
// ===========================================================================
#define STAGE_SZ 33280

__global__ __launch_bounds__(256, 2)
void attn_kernel(const int* __restrict__ tmask,
                 const float* __restrict__ mb_raw,
                 const int* __restrict__ bsp)
{
    extern __shared__ __align__(16) char s_dyn[];

    const int tid  = threadIdx.x;
    const int w    = tid >> 5;
    const int lane = tid & 31;
    const int bh   = blockIdx.y;
    const int b    = bh / NH;
    const int h    = bh - b * NH;
    const int qb   = blockIdx.x * 128;

    const float* Qg = g_q + (size_t)bh * SEQ * HD;
    const char*  KH = (const char*)g_kh + (size_t)bh * NT * 8192;
    const char*  VH = (const char*)g_vh + (size_t)bh * NT * 8192;
    const int*   MK = tmask + b * SEQ;

    const uint32_t sb0 = smem_u32(s_dyn);

    float bs;
    {
        int iv = bsp[0];
        bs = (iv > -1000000 && iv < 1000000) ? (float)iv : __int_as_float(iv);
    }
    float G1 = 0.5f * tanhf(mb_raw[h * 3 + 0]) * bs;
    float G2 = 0.5f * tanhf(mb_raw[h * 3 + 1]) * bs;
    float G3 = 0.5f * tanhf(mb_raw[h * 3 + 2]) * bs;
    const float b01 = fminf(2.0f, fmaxf(-2.0f, G2));
    const float b10 = fminf(2.0f, fmaxf(-2.0f, G1));
    const float b11 = fminf(2.0f, fmaxf(-2.0f, G1 + G2 + G3));

    const int rA = qb + w * 16 + (lane >> 2);
    const int cb = (lane & 3) * 2;
    const int miA = MK[rA];
    const int miB = MK[rA + 8];
    // exp2 domain: fold log2(e) into scale and bias (incl. the -4 shift)
    const float bm0A = ((miA ? b10 : 0.0f) - 4.0f) * L2E;
    const float bm1A = ((miA ? b11 : b01 ) - 4.0f) * L2E;
    const float bm0B = ((miB ? b10 : 0.0f) - 4.0f) * L2E;
    const float bm1B = ((miB ? b11 : b01 ) - 4.0f) * L2E;
    const float SC = 0.125f * L2E;

    uint32_t qhi[16];
    {
        const float* qA = Qg + (size_t)rA * HD + cb;
        const float* qB = qA + 8 * HD;
        #pragma unroll
        for (int kc = 0; kc < 4; kc++) {
            float2 fA0 = *(const float2*)(qA + kc * 16);
            float2 fB0 = *(const float2*)(qB + kc * 16);
            float2 fA1 = *(const float2*)(qA + kc * 16 + 8);
            float2 fB1 = *(const float2*)(qB + kc * 16 + 8);
            qhi[kc*4+0] = pack_h2(fA0.x, fA0.y);
            qhi[kc*4+1] = pack_h2(fB0.x, fB0.y);
            qhi[kc*4+2] = pack_h2(fA1.x, fA1.y);
            qhi[kc*4+3] = pack_h2(fB1.x, fB1.y);
        }
    }

    const int joK = (lane & 7) + ((lane >> 4) & 1) * 8;
    const int doK = ((lane >> 3) & 1) * 8;
    const uint32_t lK = (uint32_t)(joK * 128 + doK * 2);
    const uint32_t xK = (uint32_t)((joK & 7) << 4);
    const int joV = (lane & 7) + ((lane >> 3) & 1) * 8;
    const int doV = ((lane >> 4) & 1) * 8;
    const uint32_t lV = (uint32_t)(joV * 128 + doV * 2);
    const uint32_t xV = (uint32_t)((joV & 7) << 4);

    float o[8][4];
    #pragma unroll
    for (int i = 0; i < 8; i++)
        #pragma unroll
        for (int jx = 0; jx < 4; jx++) o[i][jx] = 0.0f;
    float lA = 0.0f, lB = 0.0f;

    // ---- prefetch tile-pair 0 (32 KB data + 512 B mask) ----
    {
        uint32_t sb = sb0;
        #pragma unroll
        for (int i = 0; i < 4; i++) {
            uint32_t c = (uint32_t)tid * 16 + i * 4096;
            cp_async16(sb + c,         KH + c);
            cp_async16(sb + 16384 + c, VH + c);
        }
        if (tid < 32) cp_async16(sb + 32768 + tid * 16, MK + tid * 4);
        CP_COMMIT();
    }

    for (int kp = 0; kp < NTP; kp++) {
        const int s = kp & 1;
        if (kp + 1 < NTP) {
            uint32_t sb = sb0 + (s ^ 1) * STAGE_SZ;
            size_t toff = (size_t)(kp + 1) * 16384;
            #pragma unroll
            for (int i = 0; i < 4; i++) {
                uint32_t c = (uint32_t)tid * 16 + i * 4096;
                cp_async16(sb + c,         KH + toff + c);
                cp_async16(sb + 16384 + c, VH + toff + c);
            }
            if (tid < 32) cp_async16(sb + 32768 + tid * 16, MK + (kp + 1) * 128 + tid * 4);
            CP_COMMIT();
            CP_WAIT1();
        } else {
            CP_WAIT0();
        }
        __syncthreads();

        const uint32_t stg = sb0 + s * STAGE_SZ;

        #pragma unroll
        for (int sub = 0; sub < 2; sub++) {
            const uint32_t khiA = stg + sub * 8192;
            const uint32_t vhiA = stg + 16384 + sub * 8192;
            const int* mjs = (const int*)(s_dyn + s * STAGE_SZ + 32768 + sub * 256);

            #pragma unroll
            for (int half = 0; half < 2; half++) {
                float sf[4][4];
                #pragma unroll
                for (int i = 0; i < 4; i++)
                    #pragma unroll
                    for (int jx = 0; jx < 4; jx++) sf[i][jx] = 0.0f;

                #pragma unroll
                for (int nb2 = 0; nb2 < 2; nb2++) {
                    #pragma unroll
                    for (int kc = 0; kc < 4; kc++) {
                        uint32_t off = (uint32_t)((half * 2 + nb2) * 2048 + kc * 32) + lK;
                        uint32_t bh0, bh1, bh2, bh3;
                        ldsm_x4(bh0, bh1, bh2, bh3, (khiA + off) ^ xK);
                        mma16816(sf[2*nb2],   qhi[kc*4+0], qhi[kc*4+1], qhi[kc*4+2], qhi[kc*4+3], bh0, bh1);
                        mma16816(sf[2*nb2+1], qhi[kc*4+0], qhi[kc*4+1], qhi[kc*4+2], qhi[kc*4+3], bh2, bh3);
                    }
                }

                uint32_t phi[8];
                #pragma unroll
                for (int nb = 0; nb < 4; nb++) {
                    int j0 = half * 32 + nb * 8 + cb;
                    int mj0 = mjs[j0], mj1 = mjs[j0 + 1];
                    float bA0 = mj0 ? bm1A : bm0A;
                    float bA1 = mj1 ? bm1A : bm0A;
                    float bB0 = mj0 ? bm1B : bm0B;
                    float bB1 = mj1 ? bm1B : bm0B;
                    float pA0 = exp2f(fmaf(sf[nb][0], SC, bA0));
                    float pA1 = exp2f(fmaf(sf[nb][1], SC, bA1));
                    float pB0 = exp2f(fmaf(sf[nb][2], SC, bB0));
                    float pB1 = exp2f(fmaf(sf[nb][3], SC, bB1));
                    lA += pA0 + pA1;
                    lB += pB0 + pB1;
                    phi[nb*2+0] = pack_h2(pA0, pA1);
                    phi[nb*2+1] = pack_h2(pB0, pB1);
                }

                #pragma unroll
                for (int db2 = 0; db2 < 4; db2++) {
                    #pragma unroll
                    for (int kc = 0; kc < 2; kc++) {
                        uint32_t off = (uint32_t)((half * 2 + kc) * 2048 + db2 * 32) + lV;
                        uint32_t v0, v1, v2, v3;
                        ldsm_x4_t(v0, v1, v2, v3, (vhiA + off) ^ xV);
                        mma16816(o[2*db2],   phi[4*kc+0], phi[4*kc+1], phi[4*kc+2], phi[4*kc+3], v0, v1);
                        mma16816(o[2*db2+1], phi[4*kc+0], phi[4*kc+1], phi[4*kc+2], phi[4*kc+3], v2, v3);
                    }
                }
            }
        }
        __syncthreads();
    }

    // ---- epilogue: normalize and write fp16 hi/lo y-images ----
    lA += __shfl_xor_sync(0xffffffffu, lA, 1);
    lA += __shfl_xor_sync(0xffffffffu, lA, 2);
    lB += __shfl_xor_sync(0xffffffffu, lB, 1);
    lB += __shfl_xor_sync(0xffffffffu, lB, 2);
    float iA = 1.0f / lA, iB = 1.0f / lB;

    #pragma unroll
    for (int rp = 0; rp < 2; rp++) {
        int t = rA + rp * 8;
        float inv = rp ? iB : iA;
        int gr = b * SEQ + t;
        int rt = gr >> 7, rl = gr & 127;
        #pragma unroll
        for (int db = 0; db < 8; db++) {
            int c = h * 64 + db * 8 + cb;
            int kb = c >> 5;
            size_t base = (size_t)(rt * NKB + kb) * 8192;
            uint32_t off = sw64((uint32_t)(rl * 64 + (c & 31) * 2));
            float v0 = o[db][rp * 2 + 0] * inv;
            float v1 = o[db][rp * 2 + 1] * inv;
            *(uint32_t*)(g_yh + base + off) = pack_h2(v0, v1);
            *(uint32_t*)(g_yl + base + off) = pack_h2(lo_res(v0), lo_res(v1));
        }
    }
}

// ---------------------------------------------------------------------------
extern "C" void kernel_launch(void* const* d_in, const int* in_sizes, int n_in,
                              void* d_out, int out_size)
{
    const float* x    = (const float*)d_in[0];
    const float* cosp = (const float*)d_in[1];
    const float* sinp = (const float*)d_in[2];
    const int*   tmsk = (const int*)  d_in[3];
    const float* Wq   = (const float*)d_in[4];
    const float* Wk   = (const float*)d_in[5];
    const float* Wv   = (const float*)d_in[6];
    const float* Wpr  = (const float*)d_in[7];
    const float* mbr  = (const float*)d_in[8];
    const int*   bsp  = (const int*)  d_in[9];
    float* out = (float*)d_out;

    cudaFuncSetAttribute(attn_kernel,
                         cudaFuncAttributeMaxDynamicSharedMemorySize, 2 * STAGE_SZ);

    conv_kernel<<<NRT * NKB + 4 * NJT * NKB, 256>>>(x, Wq, Wk, Wv, Wpr);

    gemm_img<1, 0, -1, true ><<<dim3(NRT, NJT, 2), 256>>>(0, cosp, sinp, nullptr);
    gemm_img<3, 0,  2, false><<<dim3(NRT, NJT),    256>>>(2, nullptr, nullptr, nullptr);

    attn_kernel<<<dim3(SEQ / 128, BATCH * NH), 256, 2 * STAGE_SZ>>>(tmsk, mbr, bsp);

    gemm_img<3, 1,  3, false><<<dim3(NRT, NJT),    256>>>(3, nullptr, nullptr, out);
}